// round 1
// baseline (speedup 1.0000x reference)
#include <cuda_runtime.h>
#include <math.h>

#define D_MODEL 2048
#define SEQ     2048
#define BATCH   2
#define ROWS    (BATCH*SEQ)     /* 4096 */
#define D_FF    5504
#define NH      16
#define DK      128

/* ---------------- scratch (device globals; no cudaMalloc allowed) -------- */
__device__ float g_xn [(size_t)ROWS*D_MODEL];
__device__ float g_q  [(size_t)ROWS*D_MODEL];
__device__ float g_k  [(size_t)ROWS*D_MODEL];
__device__ float g_v  [(size_t)ROWS*D_MODEL];
__device__ float g_att[(size_t)ROWS*D_MODEL];
__device__ float g_res[(size_t)ROWS*D_MODEL];
__device__ float g_f1 [(size_t)ROWS*D_FF];
__device__ float g_f3 [(size_t)ROWS*D_FF];

/* ---------------- RMSNorm: one block per row (D=2048) -------------------- */
__global__ __launch_bounds__(256) void rmsnorm_kernel(
    const float* __restrict__ X, const float* __restrict__ g,
    float* __restrict__ Y)
{
    const int row = blockIdx.x;
    const float* x = X + (size_t)row * D_MODEL;
    float* y = Y + (size_t)row * D_MODEL;

    float ss = 0.f;
    #pragma unroll
    for (int i = threadIdx.x; i < D_MODEL/4; i += 256) {
        float4 v = ((const float4*)x)[i];
        ss += v.x*v.x + v.y*v.y + v.z*v.z + v.w*v.w;
    }
    /* warp reduce */
    #pragma unroll
    for (int off = 16; off; off >>= 1)
        ss += __shfl_xor_sync(0xffffffffu, ss, off);
    __shared__ float red[8];
    if ((threadIdx.x & 31) == 0) red[threadIdx.x >> 5] = ss;
    __syncthreads();
    float tot = red[0]+red[1]+red[2]+red[3]+red[4]+red[5]+red[6]+red[7];
    float rinv = rsqrtf(tot * (1.0f / D_MODEL) + 1e-5f);

    #pragma unroll
    for (int i = threadIdx.x; i < D_MODEL/4; i += 256) {
        float4 v = ((const float4*)x)[i];
        float4 gg = ((const float4*)g)[i];
        float4 o;
        o.x = v.x * rinv * gg.x; o.y = v.y * rinv * gg.y;
        o.z = v.z * rinv * gg.z; o.w = v.w * rinv * gg.w;
        ((float4*)y)[i] = o;
    }
}

/* ---------------- SGEMM: C[M,N] = A[M,K] * B[N,K]^T (+ R) ---------------- */
/* 128x128 tile, 256 threads, 8x8 per thread, K-step 8.                     */
__global__ __launch_bounds__(256) void gemm_nt_kernel(
    const float* __restrict__ A, const float* __restrict__ B,
    float* __restrict__ C, const float* __restrict__ R,
    int M, int N, int K)
{
    __shared__ float As[8][128];
    __shared__ float Bs[8][128];

    const int tid = threadIdx.x;
    const int bx = blockIdx.x * 128;   /* N offset */
    const int by = blockIdx.y * 128;   /* M offset */
    const int tx = tid & 15;
    const int ty = tid >> 4;

    const int lr = tid >> 1;           /* 0..127 row within tile */
    const int lc = (tid & 1) * 4;      /* 0 or 4 */

    const float* Aptr = A + (size_t)(by + lr) * K + lc;
    const float* Bptr = B + (size_t)(bx + lr) * K + lc;

    float acc[8][8];
    #pragma unroll
    for (int i = 0; i < 8; i++)
        #pragma unroll
        for (int j = 0; j < 8; j++) acc[i][j] = 0.f;

    for (int k0 = 0; k0 < K; k0 += 8) {
        float4 av = *(const float4*)(Aptr + k0);
        float4 bv = *(const float4*)(Bptr + k0);
        As[lc+0][lr] = av.x; As[lc+1][lr] = av.y;
        As[lc+2][lr] = av.z; As[lc+3][lr] = av.w;
        Bs[lc+0][lr] = bv.x; Bs[lc+1][lr] = bv.y;
        Bs[lc+2][lr] = bv.z; Bs[lc+3][lr] = bv.w;
        __syncthreads();

        #pragma unroll
        for (int kk = 0; kk < 8; kk++) {
            float4 a0 = *(const float4*)&As[kk][ty*4];
            float4 a1 = *(const float4*)&As[kk][64 + ty*4];
            float4 b0 = *(const float4*)&Bs[kk][tx*4];
            float4 b1 = *(const float4*)&Bs[kk][64 + tx*4];
            float a[8] = {a0.x,a0.y,a0.z,a0.w,a1.x,a1.y,a1.z,a1.w};
            float b[8] = {b0.x,b0.y,b0.z,b0.w,b1.x,b1.y,b1.z,b1.w};
            #pragma unroll
            for (int i = 0; i < 8; i++)
                #pragma unroll
                for (int j = 0; j < 8; j++)
                    acc[i][j] = fmaf(a[i], b[j], acc[i][j]);
        }
        __syncthreads();
    }

    #pragma unroll
    for (int i = 0; i < 8; i++) {
        int row = by + ((i < 4) ? (ty*4 + i) : (64 + ty*4 + (i-4)));
        float* Crow = C + (size_t)row * N + bx;
        float4 c0 = make_float4(acc[i][0], acc[i][1], acc[i][2], acc[i][3]);
        float4 c1 = make_float4(acc[i][4], acc[i][5], acc[i][6], acc[i][7]);
        if (R) {
            const float* Rrow = R + (size_t)row * N + bx;
            float4 r0 = *(const float4*)(Rrow + tx*4);
            float4 r1 = *(const float4*)(Rrow + 64 + tx*4);
            c0.x += r0.x; c0.y += r0.y; c0.z += r0.z; c0.w += r0.w;
            c1.x += r1.x; c1.y += r1.y; c1.z += r1.z; c1.w += r1.w;
        }
        *(float4*)(Crow + tx*4)      = c0;
        *(float4*)(Crow + 64 + tx*4) = c1;
    }
}

/* ---------------- RoPE on q and k in-place ------------------------------ */
/* layout (ROWS, D_MODEL); within head (128): pair (2i, 2i+1) uses freq i.  */
__global__ __launch_bounds__(256) void rope_kernel(
    float* __restrict__ Q, float* __restrict__ Kt)
{
    const int gid = blockIdx.x * blockDim.x + threadIdx.x; /* ROWS*1024 */
    if (gid >= ROWS * (D_MODEL/2)) return;
    const int row  = gid >> 10;       /* b*SEQ + s */
    const int p    = gid & 1023;      /* head*64 + kidx */
    const int kidx = p & 63;
    const int s    = row & (SEQ-1);

    /* freq = 10000^(-2k/128) = exp(-k * ln(10000)/64) */
    const float freq = expf(-0.14391156831212824f * (float)kidx);
    float sn, cs;
    sincosf((float)s * freq, &sn, &cs);

    const size_t base = (size_t)row * D_MODEL + (p >> 6) * DK + 2*kidx;
    {
        float x0 = Q[base], x1 = Q[base+1];
        Q[base]   = x0*cs - x1*sn;
        Q[base+1] = x0*sn + x1*cs;
    }
    {
        float x0 = Kt[base], x1 = Kt[base+1];
        Kt[base]   = x0*cs - x1*sn;
        Kt[base+1] = x0*sn + x1*cs;
    }
}

/* ---------------- causal flash attention (fp32) -------------------------- */
/* grid: (S/64, B*NH); block 256. Q/K/V in (ROWS, D_MODEL) layout,          */
/* head h occupies cols [h*128, h*128+128). Output same layout.             */
#define QPAD 132
#define PPAD 68
__global__ __launch_bounds__(256) void attn_kernel(
    const float* __restrict__ Q, const float* __restrict__ K,
    const float* __restrict__ V, float* __restrict__ O)
{
    extern __shared__ float sm[];
    float* Qs = sm;                   /* 64*132 */
    float* Ks = Qs + 64*QPAD;
    float* Vs = Ks + 64*QPAD;
    float* Ps = Vs + 64*QPAD;         /* 64*68 */

    const int qb = blockIdx.x;
    const int bh = blockIdx.y;
    const int b  = bh >> 4, h = bh & 15;
    const int tid = threadIdx.x;
    const int tx = tid & 15, ty = tid >> 4;

    const size_t base = (size_t)b * SEQ * D_MODEL + (size_t)h * DK;

    /* load Q tile (64 rows x 128) */
    for (int i = tid; i < 64*32; i += 256) {
        int r = i >> 5, c4 = (i & 31) * 4;
        float4 v = *(const float4*)(Q + base + (size_t)(qb*64 + r) * D_MODEL + c4);
        *(float4*)(Qs + r*QPAD + c4) = v;
    }

    float m[4], l[4], acc[4][8];
    #pragma unroll
    for (int i = 0; i < 4; i++) {
        m[i] = -INFINITY; l[i] = 0.f;
        #pragma unroll
        for (int j = 0; j < 8; j++) acc[i][j] = 0.f;
    }
    const float scale = 0.08838834764831845f;  /* 1/sqrt(128) */

    for (int kb = 0; kb <= qb; kb++) {
        __syncthreads();   /* previous iter's PV gemm done, Q ready */
        for (int i = tid; i < 64*32; i += 256) {
            int r = i >> 5, c4 = (i & 31) * 4;
            size_t gro = base + (size_t)(kb*64 + r) * D_MODEL + c4;
            *(float4*)(Ks + r*QPAD + c4) = *(const float4*)(K + gro);
            *(float4*)(Vs + r*QPAD + c4) = *(const float4*)(V + gro);
        }
        __syncthreads();

        /* S = Q K^T (64x64), thread computes 4x4 at (ty*4, tx*4) */
        float s[4][4];
        #pragma unroll
        for (int i = 0; i < 4; i++)
            #pragma unroll
            for (int j = 0; j < 4; j++) s[i][j] = 0.f;

        #pragma unroll 4
        for (int d = 0; d < 128; d += 4) {
            float4 qa[4], ka[4];
            #pragma unroll
            for (int i = 0; i < 4; i++)
                qa[i] = *(const float4*)(Qs + (ty*4+i)*QPAD + d);
            #pragma unroll
            for (int j = 0; j < 4; j++)
                ka[j] = *(const float4*)(Ks + (tx*4+j)*QPAD + d);
            #pragma unroll
            for (int i = 0; i < 4; i++)
                #pragma unroll
                for (int j = 0; j < 4; j++)
                    s[i][j] += qa[i].x*ka[j].x + qa[i].y*ka[j].y
                             + qa[i].z*ka[j].z + qa[i].w*ka[j].w;
        }

        const bool diag = (kb == qb);
        #pragma unroll
        for (int i = 0; i < 4; i++) {
            const int qpos = qb*64 + ty*4 + i;
            #pragma unroll
            for (int j = 0; j < 4; j++) {
                float sv = s[i][j] * scale;
                if (diag && (kb*64 + tx*4 + j > qpos)) sv = -INFINITY;
                s[i][j] = sv;
            }
            float rmax = fmaxf(fmaxf(s[i][0], s[i][1]), fmaxf(s[i][2], s[i][3]));
            #pragma unroll
            for (int off = 8; off; off >>= 1)
                rmax = fmaxf(rmax, __shfl_xor_sync(0xffffffffu, rmax, off, 16));
            float mnew = fmaxf(m[i], rmax);
            float corr = expf(m[i] - mnew);
            float rsum = 0.f;
            #pragma unroll
            for (int j = 0; j < 4; j++) {
                float pv = expf(s[i][j] - mnew);
                s[i][j] = pv; rsum += pv;
            }
            #pragma unroll
            for (int off = 8; off; off >>= 1)
                rsum += __shfl_xor_sync(0xffffffffu, rsum, off, 16);
            l[i] = l[i] * corr + rsum;
            m[i] = mnew;
            #pragma unroll
            for (int j = 0; j < 8; j++) acc[i][j] *= corr;
            *(float4*)(Ps + (ty*4+i)*PPAD + tx*4) =
                make_float4(s[i][0], s[i][1], s[i][2], s[i][3]);
        }
        __syncthreads();

        /* O += P V : thread rows ty*4..+3, cols {tx*4..+3, 64+tx*4..+3} */
        #pragma unroll 4
        for (int kk = 0; kk < 64; kk++) {
            float p0 = Ps[(ty*4+0)*PPAD + kk];
            float p1 = Ps[(ty*4+1)*PPAD + kk];
            float p2 = Ps[(ty*4+2)*PPAD + kk];
            float p3 = Ps[(ty*4+3)*PPAD + kk];
            float4 v0 = *(const float4*)(Vs + kk*QPAD + tx*4);
            float4 v1 = *(const float4*)(Vs + kk*QPAD + 64 + tx*4);
            float pv[4] = {p0, p1, p2, p3};
            #pragma unroll
            for (int i = 0; i < 4; i++) {
                acc[i][0] = fmaf(pv[i], v0.x, acc[i][0]);
                acc[i][1] = fmaf(pv[i], v0.y, acc[i][1]);
                acc[i][2] = fmaf(pv[i], v0.z, acc[i][2]);
                acc[i][3] = fmaf(pv[i], v0.w, acc[i][3]);
                acc[i][4] = fmaf(pv[i], v1.x, acc[i][4]);
                acc[i][5] = fmaf(pv[i], v1.y, acc[i][5]);
                acc[i][6] = fmaf(pv[i], v1.z, acc[i][6]);
                acc[i][7] = fmaf(pv[i], v1.w, acc[i][7]);
            }
        }
    }

    #pragma unroll
    for (int i = 0; i < 4; i++) {
        const float linv = 1.f / l[i];
        const int row = qb*64 + ty*4 + i;
        float* orow = O + base + (size_t)row * D_MODEL;
        float4 o0 = make_float4(acc[i][0]*linv, acc[i][1]*linv,
                                acc[i][2]*linv, acc[i][3]*linv);
        float4 o1 = make_float4(acc[i][4]*linv, acc[i][5]*linv,
                                acc[i][6]*linv, acc[i][7]*linv);
        *(float4*)(orow + tx*4)      = o0;
        *(float4*)(orow + 64 + tx*4) = o1;
    }
}

/* ---------------- SwiGLU: f1 = silu(f1) * f3 ----------------------------- */
__global__ __launch_bounds__(256) void swiglu_kernel(
    float* __restrict__ F1, const float* __restrict__ F3, size_t n4)
{
    size_t i = (size_t)blockIdx.x * blockDim.x + threadIdx.x;
    if (i >= n4) return;
    float4 a = ((const float4*)F1)[i];
    float4 b = ((const float4*)F3)[i];
    float4 o;
    o.x = a.x / (1.f + expf(-a.x)) * b.x;
    o.y = a.y / (1.f + expf(-a.y)) * b.y;
    o.z = a.z / (1.f + expf(-a.z)) * b.z;
    o.w = a.w / (1.f + expf(-a.w)) * b.w;
    ((float4*)F1)[i] = o;
}

/* ---------------- launch -------------------------------------------------- */
extern "C" void kernel_launch(void* const* d_in, const int* in_sizes, int n_in,
                              void* d_out, int out_size)
{
    const float* x  = (const float*)d_in[0];
    const float* Wq = (const float*)d_in[1];
    const float* Wk = (const float*)d_in[2];
    const float* Wv = (const float*)d_in[3];
    const float* Wo = (const float*)d_in[4];
    const float* W1 = (const float*)d_in[5];
    const float* W2 = (const float*)d_in[6];
    const float* W3 = (const float*)d_in[7];
    const float* g1 = (const float*)d_in[8];
    const float* g2 = (const float*)d_in[9];
    float* out = (float*)d_out;

    float *xn, *q, *k, *v, *att, *res, *f1, *f3;
    cudaGetSymbolAddress((void**)&xn,  g_xn);
    cudaGetSymbolAddress((void**)&q,   g_q);
    cudaGetSymbolAddress((void**)&k,   g_k);
    cudaGetSymbolAddress((void**)&v,   g_v);
    cudaGetSymbolAddress((void**)&att, g_att);
    cudaGetSymbolAddress((void**)&res, g_res);
    cudaGetSymbolAddress((void**)&f1,  g_f1);
    cudaGetSymbolAddress((void**)&f3,  g_f3);

    const int attn_smem = (3*64*QPAD + 64*PPAD) * (int)sizeof(float);
    cudaFuncSetAttribute(attn_kernel,
        cudaFuncAttributeMaxDynamicSharedMemorySize, attn_smem);

    /* 1. xn = rmsnorm(x, g1) */
    rmsnorm_kernel<<<ROWS, 256>>>(x, g1, xn);

    /* 2. q/k/v projections */
    dim3 gqkv(D_MODEL/128, ROWS/128);
    gemm_nt_kernel<<<gqkv, 256>>>(xn, Wq, q, nullptr, ROWS, D_MODEL, D_MODEL);
    gemm_nt_kernel<<<gqkv, 256>>>(xn, Wk, k, nullptr, ROWS, D_MODEL, D_MODEL);
    gemm_nt_kernel<<<gqkv, 256>>>(xn, Wv, v, nullptr, ROWS, D_MODEL, D_MODEL);

    /* 3. RoPE on q, k */
    rope_kernel<<<(ROWS*(D_MODEL/2) + 255)/256, 256>>>(q, k);

    /* 4. causal attention */
    attn_kernel<<<dim3(SEQ/64, BATCH*NH), 256, attn_smem>>>(q, k, v, att);

    /* 5. res = x + att @ Wo^T */
    gemm_nt_kernel<<<gqkv, 256>>>(att, Wo, res, x, ROWS, D_MODEL, D_MODEL);

    /* 6. xn2 = rmsnorm(res, g2)  (reuse xn) */
    rmsnorm_kernel<<<ROWS, 256>>>(res, g2, xn);

    /* 7. f1 = xn2 @ W1^T ; f3 = xn2 @ W3^T */
    dim3 gff(D_FF/128, ROWS/128);
    gemm_nt_kernel<<<gff, 256>>>(xn, W1, f1, nullptr, ROWS, D_FF, D_MODEL);
    gemm_nt_kernel<<<gff, 256>>>(xn, W3, f3, nullptr, ROWS, D_FF, D_MODEL);

    /* 8. f1 = silu(f1) * f3 */
    {
        size_t n4 = (size_t)ROWS * D_FF / 4;
        swiglu_kernel<<<(unsigned)((n4 + 255)/256), 256>>>(f1, f3, n4);
    }

    /* 9. out = res + f1 @ W2^T */
    gemm_nt_kernel<<<gqkv, 256>>>(f1, W2, out, res, ROWS, D_MODEL, D_FF);
}

// round 3
// speedup vs baseline: 2.1152x; 2.1152x over previous
#include <cuda_runtime.h>
#include <cuda_bf16.h>
#include <math.h>
#include <stdint.h>

#define D_MODEL 2048
#define SEQ     2048
#define BATCH   2
#define ROWS    (BATCH*SEQ)     /* 4096 */
#define D_FF    5504
#define NH      16
#define DK      128

/* ================= fp32 scratch ================= */
__device__ float g_xn [(size_t)ROWS*D_MODEL];
__device__ float g_q  [(size_t)ROWS*D_MODEL];
__device__ float g_k  [(size_t)ROWS*D_MODEL];
__device__ float g_v  [(size_t)ROWS*D_MODEL];
__device__ float g_att[(size_t)ROWS*D_MODEL];
__device__ float g_res[(size_t)ROWS*D_MODEL];
__device__ float g_f1 [(size_t)ROWS*D_FF];
__device__ float g_f3 [(size_t)ROWS*D_FF];

/* ================= bf16 hi/lo scratch ================= */
__device__ __nv_bfloat16 g_xnh[(size_t)ROWS*D_MODEL];
__device__ __nv_bfloat16 g_xnl[(size_t)ROWS*D_MODEL];
__device__ __nv_bfloat16 g_ath[(size_t)ROWS*D_MODEL];
__device__ __nv_bfloat16 g_atl[(size_t)ROWS*D_MODEL];
__device__ __nv_bfloat16 g_f1h[(size_t)ROWS*D_FF];
__device__ __nv_bfloat16 g_f1l[(size_t)ROWS*D_FF];
__device__ __nv_bfloat16 g_wqh[(size_t)D_MODEL*D_MODEL];
__device__ __nv_bfloat16 g_wql[(size_t)D_MODEL*D_MODEL];
__device__ __nv_bfloat16 g_wkh[(size_t)D_MODEL*D_MODEL];
__device__ __nv_bfloat16 g_wkl[(size_t)D_MODEL*D_MODEL];
__device__ __nv_bfloat16 g_wvh[(size_t)D_MODEL*D_MODEL];
__device__ __nv_bfloat16 g_wvl[(size_t)D_MODEL*D_MODEL];
__device__ __nv_bfloat16 g_woh[(size_t)D_MODEL*D_MODEL];
__device__ __nv_bfloat16 g_wol[(size_t)D_MODEL*D_MODEL];
__device__ __nv_bfloat16 g_w1h[(size_t)D_FF*D_MODEL];
__device__ __nv_bfloat16 g_w1l[(size_t)D_FF*D_MODEL];
__device__ __nv_bfloat16 g_w3h[(size_t)D_FF*D_MODEL];
__device__ __nv_bfloat16 g_w3l[(size_t)D_FF*D_MODEL];
__device__ __nv_bfloat16 g_w2h[(size_t)D_MODEL*D_FF];
__device__ __nv_bfloat16 g_w2l[(size_t)D_MODEL*D_FF];

/* ================= helpers ================= */
__device__ __forceinline__ uint32_t smem_u32(const void* p) {
    uint32_t a;
    asm("{ .reg .u64 t; cvta.to.shared.u64 t, %1; cvt.u32.u64 %0, t; }"
        : "=r"(a) : "l"(p));
    return a;
}

#define LDSM_X4(r0,r1,r2,r3, addr) \
    asm volatile("ldmatrix.sync.aligned.m8n8.x4.shared.b16 {%0,%1,%2,%3}, [%4];" \
        : "=r"(r0),"=r"(r1),"=r"(r2),"=r"(r3) : "r"(addr))

#define MMA16816(d, a0,a1,a2,a3, b0,b1) \
    asm volatile("mma.sync.aligned.m16n8k16.row.col.f32.bf16.bf16.f32 " \
        "{%0,%1,%2,%3}, {%4,%5,%6,%7}, {%8,%9}, {%0,%1,%2,%3};" \
        : "+f"((d)[0]),"+f"((d)[1]),"+f"((d)[2]),"+f"((d)[3]) \
        : "r"(a0),"r"(a1),"r"(a2),"r"(a3), "r"(b0),"r"(b1))

/* ================= RMSNorm ================= */
__global__ __launch_bounds__(256) void rmsnorm_kernel(
    const float* __restrict__ X, const float* __restrict__ g,
    float* __restrict__ Y)
{
    const int row = blockIdx.x;
    const float* x = X + (size_t)row * D_MODEL;
    float* y = Y + (size_t)row * D_MODEL;

    float ss = 0.f;
    #pragma unroll
    for (int i = threadIdx.x; i < D_MODEL/4; i += 256) {
        float4 v = ((const float4*)x)[i];
        ss += v.x*v.x + v.y*v.y + v.z*v.z + v.w*v.w;
    }
    #pragma unroll
    for (int off = 16; off; off >>= 1)
        ss += __shfl_xor_sync(0xffffffffu, ss, off);
    __shared__ float red[8];
    if ((threadIdx.x & 31) == 0) red[threadIdx.x >> 5] = ss;
    __syncthreads();
    float tot = red[0]+red[1]+red[2]+red[3]+red[4]+red[5]+red[6]+red[7];
    float rinv = rsqrtf(tot * (1.0f / D_MODEL) + 1e-5f);

    #pragma unroll
    for (int i = threadIdx.x; i < D_MODEL/4; i += 256) {
        float4 v = ((const float4*)x)[i];
        float4 gg = ((const float4*)g)[i];
        float4 o;
        o.x = v.x * rinv * gg.x; o.y = v.y * rinv * gg.y;
        o.z = v.z * rinv * gg.z; o.w = v.w * rinv * gg.w;
        ((float4*)y)[i] = o;
    }
}

/* ================= fp32 -> bf16 hi/lo split ================= */
__global__ __launch_bounds__(256) void split_kernel(
    const float* __restrict__ X, __nv_bfloat16* __restrict__ H,
    __nv_bfloat16* __restrict__ L, int n4)
{
    int i = blockIdx.x * blockDim.x + threadIdx.x;
    if (i >= n4) return;
    float4 v = ((const float4*)X)[i];
    float vv[4] = {v.x, v.y, v.z, v.w};
    __nv_bfloat16 h[4], l[4];
    #pragma unroll
    for (int j = 0; j < 4; j++) {
        h[j] = __float2bfloat16(vv[j]);
        l[j] = __float2bfloat16(vv[j] - __bfloat162float(h[j]));
    }
    __nv_bfloat162* H2 = (__nv_bfloat162*)H;
    __nv_bfloat162* L2 = (__nv_bfloat162*)L;
    H2[2*i+0] = __nv_bfloat162(h[0], h[1]);
    H2[2*i+1] = __nv_bfloat162(h[2], h[3]);
    L2[2*i+0] = __nv_bfloat162(l[0], l[1]);
    L2[2*i+1] = __nv_bfloat162(l[2], l[3]);
}

/* ================= bf16x3 HMMA GEMM =================
   C[M,N] = (Ah+Al)[M,K] * (Bh+Bl)[N,K]^T (+R), 3-term compensated product.
   CTA 128x128, 256 threads (8 warps, 64x32 each), K-chunk 64, 3-stage pipe. */
#define CHUNK_K     64
#define TILE_BYTES  (128*128)          /* 128 rows x 64 bf16 = 16KB */
#define STAGE_BYTES (4*TILE_BYTES)     /* Ah, Al, Bh, Bl */
#define GSTAGES     3
#define GEMM_SMEM   (GSTAGES*STAGE_BYTES)

__global__ __launch_bounds__(256, 1) void gemm_bf16x3_kernel(
    const __nv_bfloat16* __restrict__ Ah, const __nv_bfloat16* __restrict__ Al,
    const __nv_bfloat16* __restrict__ Bh, const __nv_bfloat16* __restrict__ Bl,
    float* __restrict__ C, const float* __restrict__ R,
    int M, int N, int K)
{
    extern __shared__ char smem[];
    const uint32_t sb = smem_u32(smem);
    const int tid = threadIdx.x;
    const int wid = tid >> 5, lane = tid & 31;
    const int wr = wid & 1;            /* warp row  (0..1): 64 rows */
    const int wc = wid >> 1;           /* warp col  (0..3): 32 cols */
    const int NC = K / CHUNK_K;

    const int rowA = blockIdx.y * 128;
    const int rowB = blockIdx.x * 128;

    const __nv_bfloat16* srcA_h = Ah + (size_t)rowA * K;
    const __nv_bfloat16* srcA_l = Al + (size_t)rowA * K;
    const __nv_bfloat16* srcB_h = Bh + (size_t)rowB * K;
    const __nv_bfloat16* srcB_l = Bl + (size_t)rowB * K;

    const int r0 = tid >> 3;          /* 0..31 */
    const int u  = tid & 7;           /* 16B unit in 128B row */

    #define LOAD_STAGE(chunk, s) do {                                        \
        uint32_t _stb = sb + (s) * STAGE_BYTES;                              \
        size_t _k0 = (size_t)(chunk) * CHUNK_K;                              \
        const __nv_bfloat16* _src[4] = { srcA_h + _k0, srcA_l + _k0,         \
                                         srcB_h + _k0, srcB_l + _k0 };       \
        _Pragma("unroll")                                                    \
        for (int _t = 0; _t < 4; _t++) {                                     \
            uint32_t _tb = _stb + _t * TILE_BYTES;                           \
            _Pragma("unroll")                                                \
            for (int _i = 0; _i < 4; _i++) {                                 \
                int _r = r0 + _i * 32;                                       \
                const void* _g = _src[_t] + (size_t)_r * K + u * 8;          \
                uint32_t _d = _tb + _r * 128 + ((u ^ (_r & 7)) * 16);        \
                asm volatile("cp.async.cg.shared.global [%0], [%1], 16;"     \
                             :: "r"(_d), "l"(_g));                           \
            }                                                                \
        }                                                                    \
        asm volatile("cp.async.commit_group;" ::: "memory");                 \
    } while (0)

    LOAD_STAGE(0, 0);
    if (NC > 1) LOAD_STAGE(1, 1);
    if (NC > 2) LOAD_STAGE(2, 2);

    float acc[4][4][4];
    #pragma unroll
    for (int i = 0; i < 4; i++)
        #pragma unroll
        for (int j = 0; j < 4; j++)
            #pragma unroll
            for (int c = 0; c < 4; c++) acc[i][j][c] = 0.f;

    /* ldmatrix base offsets (within a tile) for this lane */
    const int lrow = lane & 15;        /* row within 16-row frag */
    const int lu   = lane >> 4;        /* 0/1: which 16B half of kstep */

    for (int j = 0; j < NC; j++) {
        {
            int pend = NC - 1 - j; if (pend > 2) pend = 2;
            if (pend == 2)      asm volatile("cp.async.wait_group 2;" ::: "memory");
            else if (pend == 1) asm volatile("cp.async.wait_group 1;" ::: "memory");
            else                asm volatile("cp.async.wait_group 0;" ::: "memory");
        }
        __syncthreads();

        const uint32_t stb = sb + (j % GSTAGES) * STAGE_BYTES;
        const uint32_t tAh = stb;
        const uint32_t tAl = stb + TILE_BYTES;
        const uint32_t tBh = stb + 2*TILE_BYTES;
        const uint32_t tBl = stb + 3*TILE_BYTES;

        #pragma unroll
        for (int ks = 0; ks < 4; ks++) {
            const int unit = ks*2 + lu;
            uint32_t ah[4][4], al[4][4];
            #pragma unroll
            for (int mf = 0; mf < 4; mf++) {
                const int row = wr*64 + mf*16 + lrow;
                const uint32_t off = row*128 + ((unit ^ (row & 7)) << 4);
                LDSM_X4(ah[mf][0], ah[mf][1], ah[mf][2], ah[mf][3], tAh + off);
                LDSM_X4(al[mf][0], al[mf][1], al[mf][2], al[mf][3], tAl + off);
            }
            uint32_t bh[2][4], bl[2][4];
            #pragma unroll
            for (int nf2 = 0; nf2 < 2; nf2++) {
                const int row = wc*32 + nf2*16 + lrow;
                const uint32_t off = row*128 + ((unit ^ (row & 7)) << 4);
                LDSM_X4(bh[nf2][0], bh[nf2][1], bh[nf2][2], bh[nf2][3], tBh + off);
                LDSM_X4(bl[nf2][0], bl[nf2][1], bl[nf2][2], bl[nf2][3], tBl + off);
            }
            /* b frag for nfrag nf: nf2 = nf>>1, sel = nf&1:
               {r[sel], r[sel+2]} (k0-7, k8-15)                      */
            #pragma unroll
            for (int mf = 0; mf < 4; mf++) {
                #pragma unroll
                for (int nf = 0; nf < 4; nf++) {
                    const int n2 = nf >> 1, sl = nf & 1;
                    /* Ah*Bh + Ah*Bl + Al*Bh */
                    MMA16816(acc[mf][nf], ah[mf][0],ah[mf][1],ah[mf][2],ah[mf][3],
                             bh[n2][sl], bh[n2][sl+2]);
                    MMA16816(acc[mf][nf], ah[mf][0],ah[mf][1],ah[mf][2],ah[mf][3],
                             bl[n2][sl], bl[n2][sl+2]);
                    MMA16816(acc[mf][nf], al[mf][0],al[mf][1],al[mf][2],al[mf][3],
                             bh[n2][sl], bh[n2][sl+2]);
                }
            }
        }
        __syncthreads();
        if (j + GSTAGES < NC) LOAD_STAGE(j + GSTAGES, j % GSTAGES);
    }

    /* epilogue: acc[mf][nf][c]: rows wr*64+mf*16+lane/4 (+8 for c>=2),
       cols wc*32+nf*8+(lane%3)*2 */
    const int erow = rowA + wr*64 + (lane >> 2);
    const int ecol = rowB + wc*32 + (lane & 3)*2;
    #pragma unroll
    for (int mf = 0; mf < 4; mf++) {
        #pragma unroll
        for (int half = 0; half < 2; half++) {
            const int row = erow + mf*16 + half*8;
            float* crow = C + (size_t)row * N + ecol;
            const float* rrow = R ? (R + (size_t)row * N + ecol) : (const float*)0;
            #pragma unroll
            for (int nf = 0; nf < 4; nf++) {
                float2 v = make_float2(acc[mf][nf][half*2+0], acc[mf][nf][half*2+1]);
                if (rrow) {
                    float2 rv = *(const float2*)(rrow + nf*8);
                    v.x += rv.x; v.y += rv.y;
                }
                *(float2*)(crow + nf*8) = v;
            }
        }
    }
    #undef LOAD_STAGE
}

/* ================= RoPE ================= */
__global__ __launch_bounds__(256) void rope_kernel(
    float* __restrict__ Q, float* __restrict__ Kt)
{
    const int gid = blockIdx.x * blockDim.x + threadIdx.x;
    if (gid >= ROWS * (D_MODEL/2)) return;
    const int row  = gid >> 10;
    const int p    = gid & 1023;
    const int kidx = p & 63;
    const int s    = row & (SEQ-1);

    const float freq = expf(-0.14391156831212824f * (float)kidx);
    float sn, cs;
    sincosf((float)s * freq, &sn, &cs);

    const size_t base = (size_t)row * D_MODEL + (p >> 6) * DK + 2*kidx;
    {
        float x0 = Q[base], x1 = Q[base+1];
        Q[base]   = x0*cs - x1*sn;
        Q[base+1] = x0*sn + x1*cs;
    }
    {
        float x0 = Kt[base], x1 = Kt[base+1];
        Kt[base]   = x0*cs - x1*sn;
        Kt[base+1] = x0*sn + x1*cs;
    }
}

/* ================= causal flash attention (fp32) ================= */
#define QPAD 132
#define PPAD 68
__global__ __launch_bounds__(256) void attn_kernel(
    const float* __restrict__ Q, const float* __restrict__ K,
    const float* __restrict__ V, float* __restrict__ O)
{
    extern __shared__ float sm[];
    float* Qs = sm;
    float* Ks = Qs + 64*QPAD;
    float* Vs = Ks + 64*QPAD;
    float* Ps = Vs + 64*QPAD;

    const int qb = blockIdx.x;
    const int bh = blockIdx.y;
    const int b  = bh >> 4, h = bh & 15;
    const int tid = threadIdx.x;
    const int tx = tid & 15, ty = tid >> 4;

    const size_t base = (size_t)b * SEQ * D_MODEL + (size_t)h * DK;

    for (int i = tid; i < 64*32; i += 256) {
        int r = i >> 5, c4 = (i & 31) * 4;
        float4 v = *(const float4*)(Q + base + (size_t)(qb*64 + r) * D_MODEL + c4);
        *(float4*)(Qs + r*QPAD + c4) = v;
    }

    float m[4], l[4], acc[4][8];
    #pragma unroll
    for (int i = 0; i < 4; i++) {
        m[i] = -INFINITY; l[i] = 0.f;
        #pragma unroll
        for (int j = 0; j < 8; j++) acc[i][j] = 0.f;
    }
    const float scale = 0.08838834764831845f;

    for (int kb = 0; kb <= qb; kb++) {
        __syncthreads();
        for (int i = tid; i < 64*32; i += 256) {
            int r = i >> 5, c4 = (i & 31) * 4;
            size_t gro = base + (size_t)(kb*64 + r) * D_MODEL + c4;
            *(float4*)(Ks + r*QPAD + c4) = *(const float4*)(K + gro);
            *(float4*)(Vs + r*QPAD + c4) = *(const float4*)(V + gro);
        }
        __syncthreads();

        float s[4][4];
        #pragma unroll
        for (int i = 0; i < 4; i++)
            #pragma unroll
            for (int j = 0; j < 4; j++) s[i][j] = 0.f;

        #pragma unroll 4
        for (int d = 0; d < 128; d += 4) {
            float4 qa[4], ka[4];
            #pragma unroll
            for (int i = 0; i < 4; i++)
                qa[i] = *(const float4*)(Qs + (ty*4+i)*QPAD + d);
            #pragma unroll
            for (int j = 0; j < 4; j++)
                ka[j] = *(const float4*)(Ks + (tx*4+j)*QPAD + d);
            #pragma unroll
            for (int i = 0; i < 4; i++)
                #pragma unroll
                for (int j = 0; j < 4; j++)
                    s[i][j] += qa[i].x*ka[j].x + qa[i].y*ka[j].y
                             + qa[i].z*ka[j].z + qa[i].w*ka[j].w;
        }

        const bool diag = (kb == qb);
        #pragma unroll
        for (int i = 0; i < 4; i++) {
            const int qpos = qb*64 + ty*4 + i;
            #pragma unroll
            for (int j = 0; j < 4; j++) {
                float sv = s[i][j] * scale;
                if (diag && (kb*64 + tx*4 + j > qpos)) sv = -INFINITY;
                s[i][j] = sv;
            }
            float rmax = fmaxf(fmaxf(s[i][0], s[i][1]), fmaxf(s[i][2], s[i][3]));
            #pragma unroll
            for (int off = 8; off; off >>= 1)
                rmax = fmaxf(rmax, __shfl_xor_sync(0xffffffffu, rmax, off, 16));
            float mnew = fmaxf(m[i], rmax);
            float corr = expf(m[i] - mnew);
            float rsum = 0.f;
            #pragma unroll
            for (int j = 0; j < 4; j++) {
                float pv = expf(s[i][j] - mnew);
                s[i][j] = pv; rsum += pv;
            }
            #pragma unroll
            for (int off = 8; off; off >>= 1)
                rsum += __shfl_xor_sync(0xffffffffu, rsum, off, 16);
            l[i] = l[i] * corr + rsum;
            m[i] = mnew;
            #pragma unroll
            for (int j = 0; j < 8; j++) acc[i][j] *= corr;
            *(float4*)(Ps + (ty*4+i)*PPAD + tx*4) =
                make_float4(s[i][0], s[i][1], s[i][2], s[i][3]);
        }
        __syncthreads();

        #pragma unroll 4
        for (int kk = 0; kk < 64; kk++) {
            float p0 = Ps[(ty*4+0)*PPAD + kk];
            float p1 = Ps[(ty*4+1)*PPAD + kk];
            float p2 = Ps[(ty*4+2)*PPAD + kk];
            float p3 = Ps[(ty*4+3)*PPAD + kk];
            float4 v0 = *(const float4*)(Vs + kk*QPAD + tx*4);
            float4 v1 = *(const float4*)(Vs + kk*QPAD + 64 + tx*4);
            float pv[4] = {p0, p1, p2, p3};
            #pragma unroll
            for (int i = 0; i < 4; i++) {
                acc[i][0] = fmaf(pv[i], v0.x, acc[i][0]);
                acc[i][1] = fmaf(pv[i], v0.y, acc[i][1]);
                acc[i][2] = fmaf(pv[i], v0.z, acc[i][2]);
                acc[i][3] = fmaf(pv[i], v0.w, acc[i][3]);
                acc[i][4] = fmaf(pv[i], v1.x, acc[i][4]);
                acc[i][5] = fmaf(pv[i], v1.y, acc[i][5]);
                acc[i][6] = fmaf(pv[i], v1.z, acc[i][6]);
                acc[i][7] = fmaf(pv[i], v1.w, acc[i][7]);
            }
        }
    }

    #pragma unroll
    for (int i = 0; i < 4; i++) {
        const float linv = 1.f / l[i];
        const int row = qb*64 + ty*4 + i;
        float* orow = O + base + (size_t)row * D_MODEL;
        float4 o0 = make_float4(acc[i][0]*linv, acc[i][1]*linv,
                                acc[i][2]*linv, acc[i][3]*linv);
        float4 o1 = make_float4(acc[i][4]*linv, acc[i][5]*linv,
                                acc[i][6]*linv, acc[i][7]*linv);
        *(float4*)(orow + tx*4)      = o0;
        *(float4*)(orow + 64 + tx*4) = o1;
    }
}

/* ================= SwiGLU ================= */
__global__ __launch_bounds__(256) void swiglu_kernel(
    float* __restrict__ F1, const float* __restrict__ F3, size_t n4)
{
    size_t i = (size_t)blockIdx.x * blockDim.x + threadIdx.x;
    if (i >= n4) return;
    float4 a = ((const float4*)F1)[i];
    float4 b = ((const float4*)F3)[i];
    float4 o;
    o.x = a.x / (1.f + expf(-a.x)) * b.x;
    o.y = a.y / (1.f + expf(-a.y)) * b.y;
    o.z = a.z / (1.f + expf(-a.z)) * b.z;
    o.w = a.w / (1.f + expf(-a.w)) * b.w;
    ((float4*)F1)[i] = o;
}

/* ================= launch ================= */
static inline void split_launch(const float* x, __nv_bfloat16* h,
                                __nv_bfloat16* l, size_t n)
{
    int n4 = (int)(n / 4);
    split_kernel<<<(n4 + 255)/256, 256>>>(x, h, l, n4);
}

extern "C" void kernel_launch(void* const* d_in, const int* in_sizes, int n_in,
                              void* d_out, int out_size)
{
    const float* x  = (const float*)d_in[0];
    const float* Wq = (const float*)d_in[1];
    const float* Wk = (const float*)d_in[2];
    const float* Wv = (const float*)d_in[3];
    const float* Wo = (const float*)d_in[4];
    const float* W1 = (const float*)d_in[5];
    const float* W2 = (const float*)d_in[6];
    const float* W3 = (const float*)d_in[7];
    const float* g1 = (const float*)d_in[8];
    const float* g2 = (const float*)d_in[9];
    float* out = (float*)d_out;

    float *xn, *q, *k, *v, *att, *res, *f1, *f3;
    cudaGetSymbolAddress((void**)&xn,  g_xn);
    cudaGetSymbolAddress((void**)&q,   g_q);
    cudaGetSymbolAddress((void**)&k,   g_k);
    cudaGetSymbolAddress((void**)&v,   g_v);
    cudaGetSymbolAddress((void**)&att, g_att);
    cudaGetSymbolAddress((void**)&res, g_res);
    cudaGetSymbolAddress((void**)&f1,  g_f1);
    cudaGetSymbolAddress((void**)&f3,  g_f3);

    __nv_bfloat16 *xnh,*xnl,*ath,*atl,*f1h,*f1l;
    __nv_bfloat16 *wqh,*wql,*wkh,*wkl,*wvh,*wvl,*woh,*wol,*w1h,*w1l,*w3h,*w3l,*w2h,*w2l;
    cudaGetSymbolAddress((void**)&xnh, g_xnh); cudaGetSymbolAddress((void**)&xnl, g_xnl);
    cudaGetSymbolAddress((void**)&ath, g_ath); cudaGetSymbolAddress((void**)&atl, g_atl);
    cudaGetSymbolAddress((void**)&f1h, g_f1h); cudaGetSymbolAddress((void**)&f1l, g_f1l);
    cudaGetSymbolAddress((void**)&wqh, g_wqh); cudaGetSymbolAddress((void**)&wql, g_wql);
    cudaGetSymbolAddress((void**)&wkh, g_wkh); cudaGetSymbolAddress((void**)&wkl, g_wkl);
    cudaGetSymbolAddress((void**)&wvh, g_wvh); cudaGetSymbolAddress((void**)&wvl, g_wvl);
    cudaGetSymbolAddress((void**)&woh, g_woh); cudaGetSymbolAddress((void**)&wol, g_wol);
    cudaGetSymbolAddress((void**)&w1h, g_w1h); cudaGetSymbolAddress((void**)&w1l, g_w1l);
    cudaGetSymbolAddress((void**)&w3h, g_w3h); cudaGetSymbolAddress((void**)&w3l, g_w3l);
    cudaGetSymbolAddress((void**)&w2h, g_w2h); cudaGetSymbolAddress((void**)&w2l, g_w2l);

    cudaFuncSetAttribute(gemm_bf16x3_kernel,
        cudaFuncAttributeMaxDynamicSharedMemorySize, GEMM_SMEM);
    const int attn_smem = (3*64*QPAD + 64*PPAD) * (int)sizeof(float);
    cudaFuncSetAttribute(attn_kernel,
        cudaFuncAttributeMaxDynamicSharedMemorySize, attn_smem);

    /* weight splits */
    split_launch(Wq, wqh, wql, (size_t)D_MODEL*D_MODEL);
    split_launch(Wk, wkh, wkl, (size_t)D_MODEL*D_MODEL);
    split_launch(Wv, wvh, wvl, (size_t)D_MODEL*D_MODEL);
    split_launch(Wo, woh, wol, (size_t)D_MODEL*D_MODEL);
    split_launch(W1, w1h, w1l, (size_t)D_FF*D_MODEL);
    split_launch(W3, w3h, w3l, (size_t)D_FF*D_MODEL);
    split_launch(W2, w2h, w2l, (size_t)D_MODEL*D_FF);

    /* 1. xn = rmsnorm(x, g1); split */
    rmsnorm_kernel<<<ROWS, 256>>>(x, g1, xn);
    split_launch(xn, xnh, xnl, (size_t)ROWS*D_MODEL);

    /* 2. q/k/v projections on tensor cores */
    dim3 gqkv(D_MODEL/128, ROWS/128);
    gemm_bf16x3_kernel<<<gqkv, 256, GEMM_SMEM>>>(xnh, xnl, wqh, wql, q, nullptr,
                                                 ROWS, D_MODEL, D_MODEL);
    gemm_bf16x3_kernel<<<gqkv, 256, GEMM_SMEM>>>(xnh, xnl, wkh, wkl, k, nullptr,
                                                 ROWS, D_MODEL, D_MODEL);
    gemm_bf16x3_kernel<<<gqkv, 256, GEMM_SMEM>>>(xnh, xnl, wvh, wvl, v, nullptr,
                                                 ROWS, D_MODEL, D_MODEL);

    /* 3. RoPE */
    rope_kernel<<<(ROWS*(D_MODEL/2) + 255)/256, 256>>>(q, k);

    /* 4. attention (fp32) */
    attn_kernel<<<dim3(SEQ/64, BATCH*NH), 256, attn_smem>>>(q, k, v, att);

    /* 5. res = x + att @ Wo^T */
    split_launch(att, ath, atl, (size_t)ROWS*D_MODEL);
    gemm_bf16x3_kernel<<<gqkv, 256, GEMM_SMEM>>>(ath, atl, woh, wol, res, x,
                                                 ROWS, D_MODEL, D_MODEL);

    /* 6. xn2 = rmsnorm(res); split */
    rmsnorm_kernel<<<ROWS, 256>>>(res, g2, xn);
    split_launch(xn, xnh, xnl, (size_t)ROWS*D_MODEL);

    /* 7. f1, f3 */
    dim3 gff(D_FF/128, ROWS/128);
    gemm_bf16x3_kernel<<<gff, 256, GEMM_SMEM>>>(xnh, xnl, w1h, w1l, f1, nullptr,
                                                ROWS, D_FF, D_MODEL);
    gemm_bf16x3_kernel<<<gff, 256, GEMM_SMEM>>>(xnh, xnl, w3h, w3l, f3, nullptr,
                                                ROWS, D_FF, D_MODEL);

    /* 8. swiglu + split */
    {
        size_t n4 = (size_t)ROWS * D_FF / 4;
        swiglu_kernel<<<(unsigned)((n4 + 255)/256), 256>>>(f1, f3, n4);
    }
    split_launch(f1, f1h, f1l, (size_t)ROWS*D_FF);

    /* 9. out = res + f1 @ W2^T */
    gemm_bf16x3_kernel<<<gqkv, 256, GEMM_SMEM>>>(f1h, f1l, w2h, w2l, out, res,
                                                 ROWS, D_MODEL, D_FF);
}

// round 4
// speedup vs baseline: 2.9252x; 1.3830x over previous
#include <cuda_runtime.h>
#include <cuda_bf16.h>
#include <math.h>
#include <stdint.h>

#define D_MODEL 2048
#define SEQ     2048
#define BATCH   2
#define ROWS    (BATCH*SEQ)     /* 4096 */
#define D_FF    5504
#define NH      16
#define DK      128

/* ================= fp32 scratch ================= */
__device__ float g_q  [(size_t)ROWS*D_MODEL];
__device__ float g_k  [(size_t)ROWS*D_MODEL];
__device__ float g_v  [(size_t)ROWS*D_MODEL];
__device__ float g_res[(size_t)ROWS*D_MODEL];
__device__ float g_f1 [(size_t)ROWS*D_FF];
__device__ float g_f3 [(size_t)ROWS*D_FF];

/* ================= bf16 hi/lo scratch ================= */
__device__ __nv_bfloat16 g_xnh[(size_t)ROWS*D_MODEL];
__device__ __nv_bfloat16 g_xnl[(size_t)ROWS*D_MODEL];
__device__ __nv_bfloat16 g_ath[(size_t)ROWS*D_MODEL];
__device__ __nv_bfloat16 g_atl[(size_t)ROWS*D_MODEL];
__device__ __nv_bfloat16 g_f1h[(size_t)ROWS*D_FF];
__device__ __nv_bfloat16 g_f1l[(size_t)ROWS*D_FF];
__device__ __nv_bfloat16 g_qh [(size_t)ROWS*D_MODEL];
__device__ __nv_bfloat16 g_ql [(size_t)ROWS*D_MODEL];
__device__ __nv_bfloat16 g_kh [(size_t)ROWS*D_MODEL];
__device__ __nv_bfloat16 g_kl [(size_t)ROWS*D_MODEL];
__device__ __nv_bfloat16 g_vth[(size_t)BATCH*NH*DK*SEQ];
__device__ __nv_bfloat16 g_vtl[(size_t)BATCH*NH*DK*SEQ];
__device__ __nv_bfloat16 g_wqh[(size_t)D_MODEL*D_MODEL];
__device__ __nv_bfloat16 g_wql[(size_t)D_MODEL*D_MODEL];
__device__ __nv_bfloat16 g_wkh[(size_t)D_MODEL*D_MODEL];
__device__ __nv_bfloat16 g_wkl[(size_t)D_MODEL*D_MODEL];
__device__ __nv_bfloat16 g_wvh[(size_t)D_MODEL*D_MODEL];
__device__ __nv_bfloat16 g_wvl[(size_t)D_MODEL*D_MODEL];
__device__ __nv_bfloat16 g_woh[(size_t)D_MODEL*D_MODEL];
__device__ __nv_bfloat16 g_wol[(size_t)D_MODEL*D_MODEL];
__device__ __nv_bfloat16 g_w1h[(size_t)D_FF*D_MODEL];
__device__ __nv_bfloat16 g_w1l[(size_t)D_FF*D_MODEL];
__device__ __nv_bfloat16 g_w3h[(size_t)D_FF*D_MODEL];
__device__ __nv_bfloat16 g_w3l[(size_t)D_FF*D_MODEL];
__device__ __nv_bfloat16 g_w2h[(size_t)D_MODEL*D_FF];
__device__ __nv_bfloat16 g_w2l[(size_t)D_MODEL*D_FF];

/* ================= helpers ================= */
__device__ __forceinline__ uint32_t smem_u32(const void* p) {
    uint32_t a;
    asm("{ .reg .u64 t; cvta.to.shared.u64 t, %1; cvt.u32.u64 %0, t; }"
        : "=r"(a) : "l"(p));
    return a;
}

#define LDSM_X4(r0,r1,r2,r3, addr) \
    asm volatile("ldmatrix.sync.aligned.m8n8.x4.shared.b16 {%0,%1,%2,%3}, [%4];" \
        : "=r"(r0),"=r"(r1),"=r"(r2),"=r"(r3) : "r"(addr))

#define MMA16816(d, a0,a1,a2,a3, b0,b1) \
    asm volatile("mma.sync.aligned.m16n8k16.row.col.f32.bf16.bf16.f32 " \
        "{%0,%1,%2,%3}, {%4,%5,%6,%7}, {%8,%9}, {%0,%1,%2,%3};" \
        : "+f"((d)[0]),"+f"((d)[1]),"+f"((d)[2]),"+f"((d)[3]) \
        : "r"(a0),"r"(a1),"r"(a2),"r"(a3), "r"(b0),"r"(b1))

__device__ __forceinline__ void split_pack2(float x, float y,
                                            uint32_t& h, uint32_t& l) {
    __nv_bfloat16 hx = __float2bfloat16(x), hy = __float2bfloat16(y);
    __nv_bfloat162 hv(hx, hy);
    __nv_bfloat162 lv(__float2bfloat16(x - __bfloat162float(hx)),
                      __float2bfloat16(y - __bfloat162float(hy)));
    h = *reinterpret_cast<uint32_t*>(&hv);
    l = *reinterpret_cast<uint32_t*>(&lv);
}

__device__ __forceinline__ void split_store2(__nv_bfloat16* H, __nv_bfloat16* L,
                                             size_t idx, float x, float y) {
    __nv_bfloat16 hx = __float2bfloat16(x), hy = __float2bfloat16(y);
    __nv_bfloat16 lx = __float2bfloat16(x - __bfloat162float(hx));
    __nv_bfloat16 ly = __float2bfloat16(y - __bfloat162float(hy));
    *reinterpret_cast<__nv_bfloat162*>(H + idx) = __nv_bfloat162(hx, hy);
    *reinterpret_cast<__nv_bfloat162*>(L + idx) = __nv_bfloat162(lx, ly);
}

/* ================= RMSNorm (+split) ================= */
__global__ __launch_bounds__(256) void rmsnorm_split_kernel(
    const float* __restrict__ X, const float* __restrict__ g,
    __nv_bfloat16* __restrict__ H, __nv_bfloat16* __restrict__ L)
{
    const int row = blockIdx.x;
    const float* x = X + (size_t)row * D_MODEL;

    float ss = 0.f;
    #pragma unroll
    for (int i = threadIdx.x; i < D_MODEL/4; i += 256) {
        float4 v = ((const float4*)x)[i];
        ss += v.x*v.x + v.y*v.y + v.z*v.z + v.w*v.w;
    }
    #pragma unroll
    for (int off = 16; off; off >>= 1)
        ss += __shfl_xor_sync(0xffffffffu, ss, off);
    __shared__ float red[8];
    if ((threadIdx.x & 31) == 0) red[threadIdx.x >> 5] = ss;
    __syncthreads();
    float tot = red[0]+red[1]+red[2]+red[3]+red[4]+red[5]+red[6]+red[7];
    float rinv = rsqrtf(tot * (1.0f / D_MODEL) + 1e-5f);

    #pragma unroll
    for (int i = threadIdx.x; i < D_MODEL/4; i += 256) {
        float4 v = ((const float4*)x)[i];
        float4 gg = ((const float4*)g)[i];
        size_t base = (size_t)row * D_MODEL + i*4;
        split_store2(H, L, base,   v.x*rinv*gg.x, v.y*rinv*gg.y);
        split_store2(H, L, base+2, v.z*rinv*gg.z, v.w*rinv*gg.w);
    }
}

/* ================= fp32 -> bf16 hi/lo split (weights) ================= */
__global__ __launch_bounds__(256) void split_kernel(
    const float* __restrict__ X, __nv_bfloat16* __restrict__ H,
    __nv_bfloat16* __restrict__ L, int n4)
{
    int i = blockIdx.x * blockDim.x + threadIdx.x;
    if (i >= n4) return;
    float4 v = ((const float4*)X)[i];
    split_store2(H, L, (size_t)i*4,   v.x, v.y);
    split_store2(H, L, (size_t)i*4+2, v.z, v.w);
}

/* ================= bf16x3 HMMA GEMM ================= */
#define CHUNK_K     64
#define TILE_BYTES  (128*128)
#define STAGE_BYTES (4*TILE_BYTES)
#define GSTAGES     3
#define GEMM_SMEM   (GSTAGES*STAGE_BYTES)

__global__ __launch_bounds__(256, 1) void gemm_bf16x3_kernel(
    const __nv_bfloat16* __restrict__ Ah, const __nv_bfloat16* __restrict__ Al,
    const __nv_bfloat16* __restrict__ Bh, const __nv_bfloat16* __restrict__ Bl,
    float* __restrict__ C, const float* __restrict__ R,
    int M, int N, int K)
{
    extern __shared__ char smem[];
    const uint32_t sb = smem_u32(smem);
    const int tid = threadIdx.x;
    const int wid = tid >> 5, lane = tid & 31;
    const int wr = wid & 1;
    const int wc = wid >> 1;
    const int NC = K / CHUNK_K;

    const int rowA = blockIdx.y * 128;
    const int rowB = blockIdx.x * 128;

    const __nv_bfloat16* srcA_h = Ah + (size_t)rowA * K;
    const __nv_bfloat16* srcA_l = Al + (size_t)rowA * K;
    const __nv_bfloat16* srcB_h = Bh + (size_t)rowB * K;
    const __nv_bfloat16* srcB_l = Bl + (size_t)rowB * K;

    const int r0 = tid >> 3;
    const int u  = tid & 7;

    #define LOAD_STAGE(chunk, s) do {                                        \
        uint32_t _stb = sb + (s) * STAGE_BYTES;                              \
        size_t _k0 = (size_t)(chunk) * CHUNK_K;                              \
        const __nv_bfloat16* _src[4] = { srcA_h + _k0, srcA_l + _k0,         \
                                         srcB_h + _k0, srcB_l + _k0 };       \
        _Pragma("unroll")                                                    \
        for (int _t = 0; _t < 4; _t++) {                                     \
            uint32_t _tb = _stb + _t * TILE_BYTES;                           \
            _Pragma("unroll")                                                \
            for (int _i = 0; _i < 4; _i++) {                                 \
                int _r = r0 + _i * 32;                                       \
                const void* _g = _src[_t] + (size_t)_r * K + u * 8;          \
                uint32_t _d = _tb + _r * 128 + ((u ^ (_r & 7)) * 16);        \
                asm volatile("cp.async.cg.shared.global [%0], [%1], 16;"     \
                             :: "r"(_d), "l"(_g));                           \
            }                                                                \
        }                                                                    \
        asm volatile("cp.async.commit_group;" ::: "memory");                 \
    } while (0)

    LOAD_STAGE(0, 0);
    if (NC > 1) LOAD_STAGE(1, 1);
    if (NC > 2) LOAD_STAGE(2, 2);

    float acc[4][4][4];
    #pragma unroll
    for (int i = 0; i < 4; i++)
        #pragma unroll
        for (int j = 0; j < 4; j++)
            #pragma unroll
            for (int c = 0; c < 4; c++) acc[i][j][c] = 0.f;

    const int lrow = lane & 15;
    const int lu   = lane >> 4;

    for (int j = 0; j < NC; j++) {
        {
            int pend = NC - 1 - j; if (pend > 2) pend = 2;
            if (pend == 2)      asm volatile("cp.async.wait_group 2;" ::: "memory");
            else if (pend == 1) asm volatile("cp.async.wait_group 1;" ::: "memory");
            else                asm volatile("cp.async.wait_group 0;" ::: "memory");
        }
        __syncthreads();

        const uint32_t stb = sb + (j % GSTAGES) * STAGE_BYTES;
        const uint32_t tAh = stb;
        const uint32_t tAl = stb + TILE_BYTES;
        const uint32_t tBh = stb + 2*TILE_BYTES;
        const uint32_t tBl = stb + 3*TILE_BYTES;

        #pragma unroll
        for (int ks = 0; ks < 4; ks++) {
            const int unit = ks*2 + lu;
            uint32_t ah[4][4], al[4][4];
            #pragma unroll
            for (int mf = 0; mf < 4; mf++) {
                const int row = wr*64 + mf*16 + lrow;
                const uint32_t off = row*128 + ((unit ^ (row & 7)) << 4);
                LDSM_X4(ah[mf][0], ah[mf][1], ah[mf][2], ah[mf][3], tAh + off);
                LDSM_X4(al[mf][0], al[mf][1], al[mf][2], al[mf][3], tAl + off);
            }
            uint32_t bh[2][4], bl[2][4];
            #pragma unroll
            for (int nf2 = 0; nf2 < 2; nf2++) {
                const int row = wc*32 + nf2*16 + lrow;
                const uint32_t off = row*128 + ((unit ^ (row & 7)) << 4);
                LDSM_X4(bh[nf2][0], bh[nf2][1], bh[nf2][2], bh[nf2][3], tBh + off);
                LDSM_X4(bl[nf2][0], bl[nf2][1], bl[nf2][2], bl[nf2][3], tBl + off);
            }
            #pragma unroll
            for (int mf = 0; mf < 4; mf++) {
                #pragma unroll
                for (int nf = 0; nf < 4; nf++) {
                    const int n2 = nf >> 1, sl = nf & 1;
                    MMA16816(acc[mf][nf], ah[mf][0],ah[mf][1],ah[mf][2],ah[mf][3],
                             bh[n2][sl], bh[n2][sl+2]);
                    MMA16816(acc[mf][nf], ah[mf][0],ah[mf][1],ah[mf][2],ah[mf][3],
                             bl[n2][sl], bl[n2][sl+2]);
                    MMA16816(acc[mf][nf], al[mf][0],al[mf][1],al[mf][2],al[mf][3],
                             bh[n2][sl], bh[n2][sl+2]);
                }
            }
        }
        __syncthreads();
        if (j + GSTAGES < NC) LOAD_STAGE(j + GSTAGES, j % GSTAGES);
    }

    const int erow = rowA + wr*64 + (lane >> 2);
    const int ecol = rowB + wc*32 + (lane & 3)*2;
    #pragma unroll
    for (int mf = 0; mf < 4; mf++) {
        #pragma unroll
        for (int half = 0; half < 2; half++) {
            const int row = erow + mf*16 + half*8;
            float* crow = C + (size_t)row * N + ecol;
            const float* rrow = R ? (R + (size_t)row * N + ecol) : (const float*)0;
            #pragma unroll
            for (int nf = 0; nf < 4; nf++) {
                float2 v = make_float2(acc[mf][nf][half*2+0], acc[mf][nf][half*2+1]);
                if (rrow) {
                    float2 rv = *(const float2*)(rrow + nf*8);
                    v.x += rv.x; v.y += rv.y;
                }
                *(float2*)(crow + nf*8) = v;
            }
        }
    }
    #undef LOAD_STAGE
}

/* ================= RoPE + split (q scaled by 1/sqrt(dk)*log2e) ========== */
__global__ __launch_bounds__(256) void rope_split_kernel(
    const float* __restrict__ Q, const float* __restrict__ Kt,
    __nv_bfloat16* __restrict__ QH, __nv_bfloat16* __restrict__ QL,
    __nv_bfloat16* __restrict__ KH, __nv_bfloat16* __restrict__ KL)
{
    const int gid = blockIdx.x * blockDim.x + threadIdx.x;
    if (gid >= ROWS * (D_MODEL/2)) return;
    const int row  = gid >> 10;
    const int p    = gid & 1023;
    const int kidx = p & 63;
    const int s    = row & (SEQ-1);

    const float QSC = 0.08838834764831845f * 1.4426950408889634f;
    const float freq = expf(-0.14391156831212824f * (float)kidx);
    float sn, cs;
    sincosf((float)s * freq, &sn, &cs);

    const size_t base = (size_t)row * D_MODEL + (p >> 6) * DK + 2*kidx;
    float q0 = Q[base], q1 = Q[base+1];
    float k0 = Kt[base], k1 = Kt[base+1];
    float qe = (q0*cs - q1*sn) * QSC;
    float qo = (q0*sn + q1*cs) * QSC;
    float ke = k0*cs - k1*sn;
    float ko = k0*sn + k1*cs;
    split_store2(QH, QL, base, qe, qo);
    split_store2(KH, KL, base, ke, ko);
}

/* ================= V transpose + split: [row][h*128+d] -> [bh][d][s] ===== */
__global__ __launch_bounds__(256) void vtrans_split_kernel(
    const float* __restrict__ V, __nv_bfloat16* __restrict__ H,
    __nv_bfloat16* __restrict__ L)
{
    __shared__ float t[32][33];
    const int s0 = blockIdx.x * 32, d0 = blockIdx.y * 32, bh = blockIdx.z;
    const int b = bh >> 4, h = bh & 15;
    const int tx = threadIdx.x & 31, ty = threadIdx.x >> 5;  /* 32 x 8 */
    #pragma unroll
    for (int j = 0; j < 4; j++) {
        int s = s0 + ty + j*8;
        t[ty + j*8][tx] = V[((size_t)(b*SEQ + s))*D_MODEL + h*DK + d0 + tx];
    }
    __syncthreads();
    #pragma unroll
    for (int j = 0; j < 4; j++) {
        int d = d0 + ty + j*8;
        float val = t[tx][ty + j*8];
        __nv_bfloat16 hi = __float2bfloat16(val);
        __nv_bfloat16 lo = __float2bfloat16(val - __bfloat162float(hi));
        size_t idx = ((size_t)bh*DK + d)*SEQ + s0 + tx;
        H[idx] = hi; L[idx] = lo;
    }
}

/* ================= HMMA causal flash attention (bf16x3) ================= */
/* CTA: 128 q-rows (8 warps x 16), 64-key blocks, 2-stage pipeline.
   smem: Qh 32K | Ql 32K | 2 x stage { Kh 16K | Kl 16K | Vh 16K | Vl 16K }  */
#define ATTN_SMEM  (192*1024)

__global__ __launch_bounds__(256, 1) void attn_hmma_kernel(
    const __nv_bfloat16* __restrict__ Qh, const __nv_bfloat16* __restrict__ Ql,
    const __nv_bfloat16* __restrict__ Kh, const __nv_bfloat16* __restrict__ Kl,
    const __nv_bfloat16* __restrict__ Vh, const __nv_bfloat16* __restrict__ Vl,
    __nv_bfloat16* __restrict__ Oh, __nv_bfloat16* __restrict__ Ol)
{
    extern __shared__ char smem[];
    const uint32_t sb  = smem_u32(smem);
    const uint32_t sQh = sb, sQl = sb + 32768;
    const int qb = (int)gridDim.x - 1 - (int)blockIdx.x;   /* heavy first */
    const int bh = blockIdx.y;
    const int b = bh >> 4, h = bh & 15;
    const int tid = threadIdx.x, wid = tid >> 5, lane = tid & 31;
    const int r0 = lane >> 2, qd = lane & 3, lrow = lane & 15, lu = lane >> 4;

    const size_t qrow0 = (size_t)b*SEQ + (size_t)qb*128;
    const size_t krow0 = (size_t)b*SEQ;
    const int hoff = h*DK;
    const size_t vbase = (size_t)bh*DK*SEQ;
    const int NKB = 2*qb + 2;

    /* Q tiles (hi+lo), folded into stage-0's commit group */
    #pragma unroll
    for (int it = 0; it < 8; it++) {
        int lin = it*256 + tid;
        int r = lin >> 4, un = lin & 15;
        uint32_t dsw = r*256 + ((un>>3)<<7) + (((un&7) ^ (r&7)) << 4);
        const void* gh = Qh + (qrow0 + r)*D_MODEL + hoff + un*8;
        const void* gl = Ql + (qrow0 + r)*D_MODEL + hoff + un*8;
        asm volatile("cp.async.cg.shared.global [%0], [%1], 16;" :: "r"(sQh+dsw), "l"(gh));
        asm volatile("cp.async.cg.shared.global [%0], [%1], 16;" :: "r"(sQl+dsw), "l"(gl));
    }

    #define LOAD_KV(kb_, s_) do {                                                  \
        uint32_t _st = sb + 65536 + (uint32_t)(s_)*65536;                          \
        size_t _kr = krow0 + (size_t)(kb_)*64;                                     \
        _Pragma("unroll")                                                          \
        for (int _it = 0; _it < 4; _it++) {                                        \
            int _lin = _it*256 + tid;                                              \
            int _r = _lin >> 4, _un = _lin & 15;                                   \
            uint32_t _d = _r*256 + ((_un>>3)<<7) + (((_un&7) ^ (_r&7)) << 4);      \
            const void* _g1 = Kh + (_kr + _r)*D_MODEL + hoff + _un*8;              \
            const void* _g2 = Kl + (_kr + _r)*D_MODEL + hoff + _un*8;              \
            asm volatile("cp.async.cg.shared.global [%0], [%1], 16;"               \
                         :: "r"(_st+_d), "l"(_g1));                                \
            asm volatile("cp.async.cg.shared.global [%0], [%1], 16;"               \
                         :: "r"(_st+16384+_d), "l"(_g2));                          \
        }                                                                          \
        _Pragma("unroll")                                                          \
        for (int _it = 0; _it < 4; _it++) {                                        \
            int _lin = _it*256 + tid;                                              \
            int _r = _lin >> 3, _u = _lin & 7;                                     \
            uint32_t _d = _r*128 + ((_u ^ (_r&7)) << 4);                           \
            const void* _g1 = Vh + vbase + (size_t)_r*SEQ + (size_t)(kb_)*64 + _u*8; \
            const void* _g2 = Vl + vbase + (size_t)_r*SEQ + (size_t)(kb_)*64 + _u*8; \
            asm volatile("cp.async.cg.shared.global [%0], [%1], 16;"               \
                         :: "r"(_st+32768+_d), "l"(_g1));                          \
            asm volatile("cp.async.cg.shared.global [%0], [%1], 16;"               \
                         :: "r"(_st+49152+_d), "l"(_g2));                          \
        }                                                                          \
        asm volatile("cp.async.commit_group;" ::: "memory");                       \
    } while (0)

    LOAD_KV(0, 0);
    LOAD_KV(1, 1);

    float m0 = -1e30f, m1 = -1e30f, l0 = 0.f, l1 = 0.f;
    float oacc[16][4];
    #pragma unroll
    for (int i = 0; i < 16; i++)
        #pragma unroll
        for (int c = 0; c < 4; c++) oacc[i][c] = 0.f;

    for (int kb = 0; kb < NKB; kb++) {
        if (kb + 1 < NKB) asm volatile("cp.async.wait_group 1;" ::: "memory");
        else              asm volatile("cp.async.wait_group 0;" ::: "memory");
        __syncthreads();
        const uint32_t st = sb + 65536 + (uint32_t)(kb & 1)*65536;

        /* ---- S = Q K^T (bf16x3) ---- */
        float sacc[8][4];
        #pragma unroll
        for (int i = 0; i < 8; i++)
            #pragma unroll
            for (int c = 0; c < 4; c++) sacc[i][c] = 0.f;

        #pragma unroll
        for (int kk = 0; kk < 8; kk++) {
            const int un = kk*2 + lu;
            const int arow = wid*16 + lrow;
            const uint32_t aoff = arow*256 + ((un>>3)<<7) + (((un&7) ^ (arow&7)) << 4);
            uint32_t ah0,ah1,ah2,ah3, al0,al1,al2,al3;
            LDSM_X4(ah0,ah1,ah2,ah3, sQh + aoff);
            LDSM_X4(al0,al1,al2,al3, sQl + aoff);
            uint32_t bh_[4][4], bl_[4][4];
            #pragma unroll
            for (int nf2 = 0; nf2 < 4; nf2++) {
                const int brow = nf2*16 + lrow;
                const uint32_t boff = brow*256 + ((un>>3)<<7) + (((un&7) ^ (brow&7)) << 4);
                LDSM_X4(bh_[nf2][0], bh_[nf2][1], bh_[nf2][2], bh_[nf2][3], st + boff);
                LDSM_X4(bl_[nf2][0], bl_[nf2][1], bl_[nf2][2], bl_[nf2][3], st + 16384 + boff);
            }
            #pragma unroll
            for (int nf = 0; nf < 8; nf++) {
                const int n2 = nf >> 1, sl = nf & 1;
                MMA16816(sacc[nf], ah0,ah1,ah2,ah3, bh_[n2][sl], bh_[n2][sl+2]);
                MMA16816(sacc[nf], ah0,ah1,ah2,ah3, bl_[n2][sl], bl_[n2][sl+2]);
                MMA16816(sacc[nf], al0,al1,al2,al3, bh_[n2][sl], bh_[n2][sl+2]);
            }
        }

        /* ---- causal mask (diagonal region only) ---- */
        if (kb >= 2*qb) {
            const int rg0 = qb*128 + wid*16 + r0;
            #pragma unroll
            for (int nf = 0; nf < 8; nf++) {
                const int cg = kb*64 + nf*8 + qd*2;
                if (cg     > rg0)     sacc[nf][0] = -1e30f;
                if (cg + 1 > rg0)     sacc[nf][1] = -1e30f;
                if (cg     > rg0 + 8) sacc[nf][2] = -1e30f;
                if (cg + 1 > rg0 + 8) sacc[nf][3] = -1e30f;
            }
        }

        /* ---- online softmax (log2 domain) ---- */
        float mx0 = -1e30f, mx1 = -1e30f;
        #pragma unroll
        for (int nf = 0; nf < 8; nf++) {
            mx0 = fmaxf(mx0, fmaxf(sacc[nf][0], sacc[nf][1]));
            mx1 = fmaxf(mx1, fmaxf(sacc[nf][2], sacc[nf][3]));
        }
        mx0 = fmaxf(mx0, __shfl_xor_sync(0xffffffffu, mx0, 1));
        mx0 = fmaxf(mx0, __shfl_xor_sync(0xffffffffu, mx0, 2));
        mx1 = fmaxf(mx1, __shfl_xor_sync(0xffffffffu, mx1, 1));
        mx1 = fmaxf(mx1, __shfl_xor_sync(0xffffffffu, mx1, 2));
        const float mn0 = fmaxf(m0, mx0), mn1 = fmaxf(m1, mx1);
        const float c0 = exp2f(m0 - mn0), c1 = exp2f(m1 - mn1);
        float s0 = 0.f, s1 = 0.f;
        #pragma unroll
        for (int nf = 0; nf < 8; nf++) {
            sacc[nf][0] = exp2f(sacc[nf][0] - mn0); s0 += sacc[nf][0];
            sacc[nf][1] = exp2f(sacc[nf][1] - mn0); s0 += sacc[nf][1];
            sacc[nf][2] = exp2f(sacc[nf][2] - mn1); s1 += sacc[nf][2];
            sacc[nf][3] = exp2f(sacc[nf][3] - mn1); s1 += sacc[nf][3];
        }
        s0 += __shfl_xor_sync(0xffffffffu, s0, 1);
        s0 += __shfl_xor_sync(0xffffffffu, s0, 2);
        s1 += __shfl_xor_sync(0xffffffffu, s1, 1);
        s1 += __shfl_xor_sync(0xffffffffu, s1, 2);
        l0 = l0*c0 + s0; l1 = l1*c1 + s1; m0 = mn0; m1 = mn1;
        #pragma unroll
        for (int nf = 0; nf < 16; nf++) {
            oacc[nf][0] *= c0; oacc[nf][1] *= c0;
            oacc[nf][2] *= c1; oacc[nf][3] *= c1;
        }

        /* ---- O += P V (bf16x3, P frags from registers) ---- */
        #pragma unroll
        for (int ks = 0; ks < 4; ks++) {
            uint32_t pah[4], pal[4];
            split_pack2(sacc[2*ks][0],   sacc[2*ks][1],   pah[0], pal[0]);
            split_pack2(sacc[2*ks][2],   sacc[2*ks][3],   pah[1], pal[1]);
            split_pack2(sacc[2*ks+1][0], sacc[2*ks+1][1], pah[2], pal[2]);
            split_pack2(sacc[2*ks+1][2], sacc[2*ks+1][3], pah[3], pal[3]);
            const int un = ks*2 + lu;
            #pragma unroll
            for (int nf2 = 0; nf2 < 8; nf2++) {
                const int vrow = nf2*16 + lrow;
                const uint32_t voff = vrow*128 + ((un ^ (vrow&7)) << 4);
                uint32_t vh0,vh1,vh2,vh3, vl0,vl1,vl2,vl3;
                LDSM_X4(vh0,vh1,vh2,vh3, st + 32768 + voff);
                LDSM_X4(vl0,vl1,vl2,vl3, st + 49152 + voff);
                MMA16816(oacc[nf2*2+0], pah[0],pah[1],pah[2],pah[3], vh0, vh2);
                MMA16816(oacc[nf2*2+0], pah[0],pah[1],pah[2],pah[3], vl0, vl2);
                MMA16816(oacc[nf2*2+0], pal[0],pal[1],pal[2],pal[3], vh0, vh2);
                MMA16816(oacc[nf2*2+1], pah[0],pah[1],pah[2],pah[3], vh1, vh3);
                MMA16816(oacc[nf2*2+1], pah[0],pah[1],pah[2],pah[3], vl1, vl3);
                MMA16816(oacc[nf2*2+1], pal[0],pal[1],pal[2],pal[3], vh1, vh3);
            }
        }
        __syncthreads();
        if (kb + 2 < NKB) LOAD_KV(kb + 2, kb & 1);
    }

    /* ---- epilogue: normalize, split to bf16 hi/lo ---- */
    const float inv0 = 1.f / l0, inv1 = 1.f / l1;
    const size_t row0 = qrow0 + wid*16 + r0;
    #pragma unroll
    for (int nf = 0; nf < 16; nf++) {
        const size_t c = (size_t)hoff + nf*8 + qd*2;
        split_store2(Oh, Ol, row0*D_MODEL + c,
                     oacc[nf][0]*inv0, oacc[nf][1]*inv0);
        split_store2(Oh, Ol, (row0+8)*D_MODEL + c,
                     oacc[nf][2]*inv1, oacc[nf][3]*inv1);
    }
    #undef LOAD_KV
}

/* ================= SwiGLU + split ================= */
__global__ __launch_bounds__(256) void swiglu_split_kernel(
    const float* __restrict__ F1, const float* __restrict__ F3,
    __nv_bfloat16* __restrict__ H, __nv_bfloat16* __restrict__ L, size_t n4)
{
    size_t i = (size_t)blockIdx.x * blockDim.x + threadIdx.x;
    if (i >= n4) return;
    float4 a = ((const float4*)F1)[i];
    float4 b = ((const float4*)F3)[i];
    float ox = a.x / (1.f + expf(-a.x)) * b.x;
    float oy = a.y / (1.f + expf(-a.y)) * b.y;
    float oz = a.z / (1.f + expf(-a.z)) * b.z;
    float ow = a.w / (1.f + expf(-a.w)) * b.w;
    split_store2(H, L, i*4,   ox, oy);
    split_store2(H, L, i*4+2, oz, ow);
}

/* ================= launch ================= */
static inline void split_launch(const float* x, __nv_bfloat16* h,
                                __nv_bfloat16* l, size_t n)
{
    int n4 = (int)(n / 4);
    split_kernel<<<(n4 + 255)/256, 256>>>(x, h, l, n4);
}

extern "C" void kernel_launch(void* const* d_in, const int* in_sizes, int n_in,
                              void* d_out, int out_size)
{
    const float* x  = (const float*)d_in[0];
    const float* Wq = (const float*)d_in[1];
    const float* Wk = (const float*)d_in[2];
    const float* Wv = (const float*)d_in[3];
    const float* Wo = (const float*)d_in[4];
    const float* W1 = (const float*)d_in[5];
    const float* W2 = (const float*)d_in[6];
    const float* W3 = (const float*)d_in[7];
    const float* g1 = (const float*)d_in[8];
    const float* g2 = (const float*)d_in[9];
    float* out = (float*)d_out;

    float *q, *k, *v, *res, *f1, *f3;
    cudaGetSymbolAddress((void**)&q,   g_q);
    cudaGetSymbolAddress((void**)&k,   g_k);
    cudaGetSymbolAddress((void**)&v,   g_v);
    cudaGetSymbolAddress((void**)&res, g_res);
    cudaGetSymbolAddress((void**)&f1,  g_f1);
    cudaGetSymbolAddress((void**)&f3,  g_f3);

    __nv_bfloat16 *xnh,*xnl,*ath,*atl,*f1h,*f1l;
    __nv_bfloat16 *qh,*ql,*kh,*kl,*vth,*vtl;
    __nv_bfloat16 *wqh,*wql,*wkh,*wkl,*wvh,*wvl,*woh,*wol,*w1h,*w1l,*w3h,*w3l,*w2h,*w2l;
    cudaGetSymbolAddress((void**)&xnh, g_xnh); cudaGetSymbolAddress((void**)&xnl, g_xnl);
    cudaGetSymbolAddress((void**)&ath, g_ath); cudaGetSymbolAddress((void**)&atl, g_atl);
    cudaGetSymbolAddress((void**)&f1h, g_f1h); cudaGetSymbolAddress((void**)&f1l, g_f1l);
    cudaGetSymbolAddress((void**)&qh,  g_qh);  cudaGetSymbolAddress((void**)&ql,  g_ql);
    cudaGetSymbolAddress((void**)&kh,  g_kh);  cudaGetSymbolAddress((void**)&kl,  g_kl);
    cudaGetSymbolAddress((void**)&vth, g_vth); cudaGetSymbolAddress((void**)&vtl, g_vtl);
    cudaGetSymbolAddress((void**)&wqh, g_wqh); cudaGetSymbolAddress((void**)&wql, g_wql);
    cudaGetSymbolAddress((void**)&wkh, g_wkh); cudaGetSymbolAddress((void**)&wkl, g_wkl);
    cudaGetSymbolAddress((void**)&wvh, g_wvh); cudaGetSymbolAddress((void**)&wvl, g_wvl);
    cudaGetSymbolAddress((void**)&woh, g_woh); cudaGetSymbolAddress((void**)&wol, g_wol);
    cudaGetSymbolAddress((void**)&w1h, g_w1h); cudaGetSymbolAddress((void**)&w1l, g_w1l);
    cudaGetSymbolAddress((void**)&w3h, g_w3h); cudaGetSymbolAddress((void**)&w3l, g_w3l);
    cudaGetSymbolAddress((void**)&w2h, g_w2h); cudaGetSymbolAddress((void**)&w2l, g_w2l);

    cudaFuncSetAttribute(gemm_bf16x3_kernel,
        cudaFuncAttributeMaxDynamicSharedMemorySize, GEMM_SMEM);
    cudaFuncSetAttribute(attn_hmma_kernel,
        cudaFuncAttributeMaxDynamicSharedMemorySize, ATTN_SMEM);

    /* weight splits */
    split_launch(Wq, wqh, wql, (size_t)D_MODEL*D_MODEL);
    split_launch(Wk, wkh, wkl, (size_t)D_MODEL*D_MODEL);
    split_launch(Wv, wvh, wvl, (size_t)D_MODEL*D_MODEL);
    split_launch(Wo, woh, wol, (size_t)D_MODEL*D_MODEL);
    split_launch(W1, w1h, w1l, (size_t)D_FF*D_MODEL);
    split_launch(W3, w3h, w3l, (size_t)D_FF*D_MODEL);
    split_launch(W2, w2h, w2l, (size_t)D_MODEL*D_FF);

    /* 1. xn = rmsnorm(x, g1) -> bf16 hi/lo */
    rmsnorm_split_kernel<<<ROWS, 256>>>(x, g1, xnh, xnl);

    /* 2. q/k/v projections */
    dim3 gqkv(D_MODEL/128, ROWS/128);
    gemm_bf16x3_kernel<<<gqkv, 256, GEMM_SMEM>>>(xnh, xnl, wqh, wql, q, nullptr,
                                                 ROWS, D_MODEL, D_MODEL);
    gemm_bf16x3_kernel<<<gqkv, 256, GEMM_SMEM>>>(xnh, xnl, wkh, wkl, k, nullptr,
                                                 ROWS, D_MODEL, D_MODEL);
    gemm_bf16x3_kernel<<<gqkv, 256, GEMM_SMEM>>>(xnh, xnl, wvh, wvl, v, nullptr,
                                                 ROWS, D_MODEL, D_MODEL);

    /* 3. RoPE + split; V transpose + split */
    rope_split_kernel<<<(ROWS*(D_MODEL/2) + 255)/256, 256>>>(q, k, qh, ql, kh, kl);
    vtrans_split_kernel<<<dim3(SEQ/32, DK/32, BATCH*NH), 256>>>(v, vth, vtl);

    /* 4. attention (HMMA bf16x3) -> bf16 hi/lo output */
    attn_hmma_kernel<<<dim3(SEQ/128, BATCH*NH), 256, ATTN_SMEM>>>(
        qh, ql, kh, kl, vth, vtl, ath, atl);

    /* 5. res = x + att @ Wo^T */
    gemm_bf16x3_kernel<<<gqkv, 256, GEMM_SMEM>>>(ath, atl, woh, wol, res, x,
                                                 ROWS, D_MODEL, D_MODEL);

    /* 6. xn2 = rmsnorm(res, g2) -> bf16 hi/lo */
    rmsnorm_split_kernel<<<ROWS, 256>>>(res, g2, xnh, xnl);

    /* 7. f1, f3 */
    dim3 gff(D_FF/128, ROWS/128);
    gemm_bf16x3_kernel<<<gff, 256, GEMM_SMEM>>>(xnh, xnl, w1h, w1l, f1, nullptr,
                                                ROWS, D_FF, D_MODEL);
    gemm_bf16x3_kernel<<<gff, 256, GEMM_SMEM>>>(xnh, xnl, w3h, w3l, f3, nullptr,
                                                ROWS, D_FF, D_MODEL);

    /* 8. swiglu -> bf16 hi/lo */
    {
        size_t n4 = (size_t)ROWS * D_FF / 4;
        swiglu_split_kernel<<<(unsigned)((n4 + 255)/256), 256>>>(f1, f3, f1h, f1l, n4);
    }

    /* 9. out = res + f1 @ W2^T */
    gemm_bf16x3_kernel<<<gqkv, 256, GEMM_SMEM>>>(f1h, f1l, w2h, w2l, out, res,
                                                 ROWS, D_MODEL, D_FF);
}

// round 9
// speedup vs baseline: 3.0629x; 1.0471x over previous
#include <cuda_runtime.h>
#include <cuda_bf16.h>
#include <math.h>
#include <stdint.h>

#define D_MODEL 2048
#define SEQ     2048
#define BATCH   2
#define ROWS    (BATCH*SEQ)     /* 4096 */
#define D_FF    5504
#define NH      16
#define DK      128

/* ================= scratch ================= */
__device__ float g_v  [(size_t)ROWS*D_MODEL];
__device__ float g_res[(size_t)ROWS*D_MODEL];

__device__ __nv_bfloat16 g_xnh[(size_t)ROWS*D_MODEL];
__device__ __nv_bfloat16 g_xnl[(size_t)ROWS*D_MODEL];
__device__ __nv_bfloat16 g_ath[(size_t)ROWS*D_MODEL];
__device__ __nv_bfloat16 g_atl[(size_t)ROWS*D_MODEL];
__device__ __nv_bfloat16 g_f1h[(size_t)ROWS*D_FF];
__device__ __nv_bfloat16 g_f1l[(size_t)ROWS*D_FF];
__device__ __nv_bfloat16 g_qh [(size_t)ROWS*D_MODEL];
__device__ __nv_bfloat16 g_ql [(size_t)ROWS*D_MODEL];
__device__ __nv_bfloat16 g_kh [(size_t)ROWS*D_MODEL];
__device__ __nv_bfloat16 g_kl [(size_t)ROWS*D_MODEL];
__device__ __nv_bfloat16 g_vth[(size_t)BATCH*NH*DK*SEQ];
__device__ __nv_bfloat16 g_vtl[(size_t)BATCH*NH*DK*SEQ];

__device__ __nv_bfloat16 g_wqkvh[(size_t)3*D_MODEL*D_MODEL];
__device__ __nv_bfloat16 g_wqkvl[(size_t)3*D_MODEL*D_MODEL];
__device__ __nv_bfloat16 g_woh  [(size_t)D_MODEL*D_MODEL];
__device__ __nv_bfloat16 g_wol  [(size_t)D_MODEL*D_MODEL];
__device__ __nv_bfloat16 g_w13h [(size_t)2*D_FF*D_MODEL];
__device__ __nv_bfloat16 g_w13l [(size_t)2*D_FF*D_MODEL];
__device__ __nv_bfloat16 g_w2h  [(size_t)D_MODEL*D_FF];
__device__ __nv_bfloat16 g_w2l  [(size_t)D_MODEL*D_FF];

/* ================= helpers ================= */
__device__ __forceinline__ uint32_t smem_u32(const void* p) {
    uint32_t a;
    asm("{ .reg .u64 t; cvta.to.shared.u64 t, %1; cvt.u32.u64 %0, t; }"
        : "=r"(a) : "l"(p));
    return a;
}

#define LDSM_X4(r0,r1,r2,r3, addr) \
    asm volatile("ldmatrix.sync.aligned.m8n8.x4.shared.b16 {%0,%1,%2,%3}, [%4];" \
        : "=r"(r0),"=r"(r1),"=r"(r2),"=r"(r3) : "r"(addr))

#define MMA16816(d, a0,a1,a2,a3, b0,b1) \
    asm volatile("mma.sync.aligned.m16n8k16.row.col.f32.bf16.bf16.f32 " \
        "{%0,%1,%2,%3}, {%4,%5,%6,%7}, {%8,%9}, {%0,%1,%2,%3};" \
        : "+f"((d)[0]),"+f"((d)[1]),"+f"((d)[2]),"+f"((d)[3]) \
        : "r"(a0),"r"(a1),"r"(a2),"r"(a3), "r"(b0),"r"(b1))

__device__ __forceinline__ void split_pack2(float x, float y,
                                            uint32_t& h, uint32_t& l) {
    __nv_bfloat16 hx = __float2bfloat16(x), hy = __float2bfloat16(y);
    __nv_bfloat162 hv(hx, hy);
    __nv_bfloat162 lv(__float2bfloat16(x - __bfloat162float(hx)),
                      __float2bfloat16(y - __bfloat162float(hy)));
    h = *reinterpret_cast<uint32_t*>(&hv);
    l = *reinterpret_cast<uint32_t*>(&lv);
}

__device__ __forceinline__ void split_store2(__nv_bfloat16* H, __nv_bfloat16* L,
                                             size_t idx, float x, float y) {
    __nv_bfloat16 hx = __float2bfloat16(x), hy = __float2bfloat16(y);
    __nv_bfloat16 lx = __float2bfloat16(x - __bfloat162float(hx));
    __nv_bfloat16 ly = __float2bfloat16(y - __bfloat162float(hy));
    *reinterpret_cast<__nv_bfloat162*>(H + idx) = __nv_bfloat162(hx, hy);
    *reinterpret_cast<__nv_bfloat162*>(L + idx) = __nv_bfloat162(lx, ly);
}

/* ================= mega weight split =================
   Wq,Wk,Wv -> wqkv (concat rows); Wo -> wo; W1,W3 -> w13 interleaved in
   64-row groups (W1 r -> (r/64)*128 + r%64; W3 r -> (r/64)*128+64 + r%64);
   W2 -> w2.  All bf16 hi/lo. */
__global__ __launch_bounds__(256) void megasplit_kernel(
    const float* __restrict__ Wq, const float* __restrict__ Wk,
    const float* __restrict__ Wv, const float* __restrict__ Wo,
    const float* __restrict__ W1, const float* __restrict__ W3,
    const float* __restrict__ W2,
    __nv_bfloat16* qkvH, __nv_bfloat16* qkvL,
    __nv_bfloat16* woH,  __nv_bfloat16* woL,
    __nv_bfloat16* w13H, __nv_bfloat16* w13L,
    __nv_bfloat16* w2H,  __nv_bfloat16* w2L)
{
    const size_t S1 = (size_t)D_MODEL*D_MODEL/4;   /* 1048576 */
    const size_t S2 = (size_t)D_FF*D_MODEL/4;      /* 2818048 */
    size_t i4 = (size_t)blockIdx.x*256 + threadIdx.x;
    if (i4 >= 4*S1 + 3*S2) return;

    float4 v; __nv_bfloat16 *H, *L; size_t d4;
    if (i4 < 3*S1) {
        size_t seg = i4 / S1, off = i4 - seg*S1;
        const float* W = (seg == 0) ? Wq : (seg == 1) ? Wk : Wv;
        v = ((const float4*)W)[off];
        H = qkvH; L = qkvL; d4 = i4;
    } else if (i4 < 4*S1) {
        size_t off = i4 - 3*S1;
        v = ((const float4*)Wo)[off];
        H = woH; L = woL; d4 = off;
    } else if (i4 < 4*S1 + 2*S2) {
        size_t off = i4 - 4*S1;
        int isW3 = off >= S2; if (isW3) off -= S2;
        v = ((const float4*)(isW3 ? W3 : W1))[off];
        size_t r = off >> 9, c = off & 511;        /* 512 float4 per row */
        size_t d = (r >> 6)*128 + (isW3 ? 64 : 0) + (r & 63);
        H = w13H; L = w13L; d4 = d*512 + c;
    } else {
        size_t off = i4 - 4*S1 - 2*S2;
        v = ((const float4*)W2)[off];
        H = w2H; L = w2L; d4 = off;
    }
    split_store2(H, L, d4*4,   v.x, v.y);
    split_store2(H, L, d4*4+2, v.z, v.w);
}

/* ================= RMSNorm (+split) ================= */
__global__ __launch_bounds__(256) void rmsnorm_split_kernel(
    const float* __restrict__ X, const float* __restrict__ g,
    __nv_bfloat16* __restrict__ H, __nv_bfloat16* __restrict__ L)
{
    const int row = blockIdx.x;
    const float* x = X + (size_t)row * D_MODEL;

    float ss = 0.f;
    #pragma unroll
    for (int i = threadIdx.x; i < D_MODEL/4; i += 256) {
        float4 v = ((const float4*)x)[i];
        ss += v.x*v.x + v.y*v.y + v.z*v.z + v.w*v.w;
    }
    #pragma unroll
    for (int off = 16; off; off >>= 1)
        ss += __shfl_xor_sync(0xffffffffu, ss, off);
    __shared__ float red[8];
    if ((threadIdx.x & 31) == 0) red[threadIdx.x >> 5] = ss;
    __syncthreads();
    float tot = red[0]+red[1]+red[2]+red[3]+red[4]+red[5]+red[6]+red[7];
    float rinv = rsqrtf(tot * (1.0f / D_MODEL) + 1e-5f);

    #pragma unroll
    for (int i = threadIdx.x; i < D_MODEL/4; i += 256) {
        float4 v = ((const float4*)x)[i];
        float4 gg = ((const float4*)g)[i];
        size_t base = (size_t)row * D_MODEL + i*4;
        split_store2(H, L, base,   v.x*rinv*gg.x, v.y*rinv*gg.y);
        split_store2(H, L, base+2, v.z*rinv*gg.z, v.w*rinv*gg.w);
    }
}

/* ================= bf16x3 HMMA GEMM (3 epilogue modes) =================
   MODE 0: C = A B^T (+R)                      [fp32 out]
   MODE 1: QKV merged; q/k: RoPE + split, v: fp32
   MODE 2: W13 merged; h = silu(f1)*f3, split                          */
#define CHUNK_K     64
#define TILE_BYTES  (128*128)
#define STAGE_BYTES (4*TILE_BYTES)
#define GSTAGES     3
#define GEMM_SMEM   (GSTAGES*STAGE_BYTES)

template<int MODE>
__global__ __launch_bounds__(256, 1) void gemm_kernel(
    const __nv_bfloat16* __restrict__ Ah, const __nv_bfloat16* __restrict__ Al,
    const __nv_bfloat16* __restrict__ Bh, const __nv_bfloat16* __restrict__ Bl,
    float* __restrict__ C, const float* __restrict__ R,
    __nv_bfloat16* __restrict__ OH, __nv_bfloat16* __restrict__ OL,
    __nv_bfloat16* __restrict__ KH2, __nv_bfloat16* __restrict__ KL2,
    int M, int N, int K)
{
    extern __shared__ char smem[];
    const uint32_t sb = smem_u32(smem);
    const int tid = threadIdx.x;
    const int wid = tid >> 5, lane = tid & 31;
    const int wr = wid & 1;
    const int wc = wid >> 1;
    const int NC = K / CHUNK_K;

    const int rowA = blockIdx.y * 128;
    const int rowB = blockIdx.x * 128;

    const __nv_bfloat16* srcA_h = Ah + (size_t)rowA * K;
    const __nv_bfloat16* srcA_l = Al + (size_t)rowA * K;
    const __nv_bfloat16* srcB_h = Bh + (size_t)rowB * K;
    const __nv_bfloat16* srcB_l = Bl + (size_t)rowB * K;

    const int r0 = tid >> 3;
    const int u  = tid & 7;

    #define LOAD_STAGE(chunk, s) do {                                        \
        uint32_t _stb = sb + (s) * STAGE_BYTES;                              \
        size_t _k0 = (size_t)(chunk) * CHUNK_K;                              \
        const __nv_bfloat16* _src[4] = { srcA_h + _k0, srcA_l + _k0,         \
                                         srcB_h + _k0, srcB_l + _k0 };       \
        _Pragma("unroll")                                                    \
        for (int _t = 0; _t < 4; _t++) {                                     \
            uint32_t _tb = _stb + _t * TILE_BYTES;                           \
            _Pragma("unroll")                                                \
            for (int _i = 0; _i < 4; _i++) {                                 \
                int _r = r0 + _i * 32;                                       \
                const void* _g = _src[_t] + (size_t)_r * K + u * 8;          \
                uint32_t _d = _tb + _r * 128 + ((u ^ (_r & 7)) * 16);        \
                asm volatile("cp.async.cg.shared.global [%0], [%1], 16;"     \
                             :: "r"(_d), "l"(_g));                           \
            }                                                                \
        }                                                                    \
        asm volatile("cp.async.commit_group;" ::: "memory");                 \
    } while (0)

    LOAD_STAGE(0, 0);
    if (NC > 1) LOAD_STAGE(1, 1);
    if (NC > 2) LOAD_STAGE(2, 2);

    float acc[4][4][4];
    #pragma unroll
    for (int i = 0; i < 4; i++)
        #pragma unroll
        for (int j = 0; j < 4; j++)
            #pragma unroll
            for (int c = 0; c < 4; c++) acc[i][j][c] = 0.f;

    const int lrow = lane & 15;
    const int lu   = lane >> 4;

    for (int j = 0; j < NC; j++) {
        {
            int pend = NC - 1 - j; if (pend > 2) pend = 2;
            if (pend == 2)      asm volatile("cp.async.wait_group 2;" ::: "memory");
            else if (pend == 1) asm volatile("cp.async.wait_group 1;" ::: "memory");
            else                asm volatile("cp.async.wait_group 0;" ::: "memory");
        }
        __syncthreads();

        const uint32_t stb = sb + (j % GSTAGES) * STAGE_BYTES;
        const uint32_t tAh = stb;
        const uint32_t tAl = stb + TILE_BYTES;
        const uint32_t tBh = stb + 2*TILE_BYTES;
        const uint32_t tBl = stb + 3*TILE_BYTES;

        #pragma unroll
        for (int ks = 0; ks < 4; ks++) {
            const int unit = ks*2 + lu;
            uint32_t ah[4][4], al[4][4];
            #pragma unroll
            for (int mf = 0; mf < 4; mf++) {
                const int row = wr*64 + mf*16 + lrow;
                const uint32_t off = row*128 + ((unit ^ (row & 7)) << 4);
                LDSM_X4(ah[mf][0], ah[mf][1], ah[mf][2], ah[mf][3], tAh + off);
                LDSM_X4(al[mf][0], al[mf][1], al[mf][2], al[mf][3], tAl + off);
            }
            uint32_t bh[2][4], bl[2][4];
            #pragma unroll
            for (int nf2 = 0; nf2 < 2; nf2++) {
                const int row = wc*32 + nf2*16 + lrow;
                const uint32_t off = row*128 + ((unit ^ (row & 7)) << 4);
                LDSM_X4(bh[nf2][0], bh[nf2][1], bh[nf2][2], bh[nf2][3], tBh + off);
                LDSM_X4(bl[nf2][0], bl[nf2][1], bl[nf2][2], bl[nf2][3], tBl + off);
            }
            #pragma unroll
            for (int mf = 0; mf < 4; mf++) {
                #pragma unroll
                for (int nf = 0; nf < 4; nf++) {
                    const int n2 = nf >> 1, sl = nf & 1;
                    MMA16816(acc[mf][nf], ah[mf][0],ah[mf][1],ah[mf][2],ah[mf][3],
                             bh[n2][sl], bh[n2][sl+2]);
                    MMA16816(acc[mf][nf], ah[mf][0],ah[mf][1],ah[mf][2],ah[mf][3],
                             bl[n2][sl], bl[n2][sl+2]);
                    MMA16816(acc[mf][nf], al[mf][0],al[mf][1],al[mf][2],al[mf][3],
                             bh[n2][sl], bh[n2][sl+2]);
                }
            }
        }
        __syncthreads();
        if (j + GSTAGES < NC) LOAD_STAGE(j + GSTAGES, j % GSTAGES);
    }

    const int erowL = wr*64 + (lane >> 2);        /* local row base */
    const int ecolL = wc*32 + (lane & 3)*2;       /* local col base */

    if (MODE == 0) {
        const int erow = rowA + erowL;
        const int ecol = rowB + ecolL;
        #pragma unroll
        for (int mf = 0; mf < 4; mf++) {
            #pragma unroll
            for (int half = 0; half < 2; half++) {
                const int row = erow + mf*16 + half*8;
                float* crow = C + (size_t)row * N + ecol;
                const float* rrow = R ? (R + (size_t)row * N + ecol) : (const float*)0;
                #pragma unroll
                for (int nf = 0; nf < 4; nf++) {
                    float2 v = make_float2(acc[mf][nf][half*2+0], acc[mf][nf][half*2+1]);
                    if (rrow) {
                        float2 rv = *(const float2*)(rrow + nf*8);
                        v.x += rv.x; v.y += rv.y;
                    }
                    *(float2*)(crow + nf*8) = v;
                }
            }
        }
    } else if (MODE == 1) {
        /* q/k: RoPE + split; v: fp32. seg by bx/16 */
        const int seg = blockIdx.x >> 4;
        const int colT0 = ((blockIdx.x & 15) << 7) + ecolL;
        const float QSC = 0.08838834764831845f * 1.4426950408889634f;
        #pragma unroll
        for (int mf = 0; mf < 4; mf++) {
            #pragma unroll
            for (int half = 0; half < 2; half++) {
                const int rowg = rowA + erowL + mf*16 + half*8;
                const int s = rowg & (SEQ-1);
                #pragma unroll
                for (int nf = 0; nf < 4; nf++) {
                    const int col = colT0 + nf*8;
                    float v0 = acc[mf][nf][half*2+0];
                    float v1 = acc[mf][nf][half*2+1];
                    if (seg == 2) {
                        *(float2*)(C + (size_t)rowg*D_MODEL + col) = make_float2(v0, v1);
                    } else {
                        const int kidx = (col & 127) >> 1;
                        const float freq = expf(-0.14391156831212824f * (float)kidx);
                        float sn, cs;
                        sincosf((float)s * freq, &sn, &cs);
                        float e = v0*cs - v1*sn;
                        float o = v0*sn + v1*cs;
                        if (seg == 0) {
                            split_store2(OH, OL, (size_t)rowg*D_MODEL + col,
                                         e*QSC, o*QSC);
                        } else {
                            split_store2(KH2, KL2, (size_t)rowg*D_MODEL + col, e, o);
                        }
                    }
                }
            }
        }
    } else {
        /* MODE 2: tile = 64 f1-cols (wc 0,1) + 64 f3-cols (wc 2,3), same
           global col range. Exchange f3 via smem, emit h = silu(f1)*f3. */
        float* sx = (float*)smem;              /* [128][68] fp32 */
        __syncthreads();
        if (wc >= 2) {
            #pragma unroll
            for (int mf = 0; mf < 4; mf++) {
                #pragma unroll
                for (int half = 0; half < 2; half++) {
                    const int rl = erowL + mf*16 + half*8;
                    #pragma unroll
                    for (int nf = 0; nf < 4; nf++) {
                        const int jj = ecolL - 64 + nf*8;
                        sx[rl*68 + jj]     = acc[mf][nf][half*2+0];
                        sx[rl*68 + jj + 1] = acc[mf][nf][half*2+1];
                    }
                }
            }
        }
        __syncthreads();
        if (wc < 2) {
            #pragma unroll
            for (int mf = 0; mf < 4; mf++) {
                #pragma unroll
                for (int half = 0; half < 2; half++) {
                    const int rl = erowL + mf*16 + half*8;
                    const size_t rowg = (size_t)(rowA + rl);
                    #pragma unroll
                    for (int nf = 0; nf < 4; nf++) {
                        const int jj = ecolL + nf*8;
                        float a0 = acc[mf][nf][half*2+0];
                        float a1 = acc[mf][nf][half*2+1];
                        float b0 = sx[rl*68 + jj];
                        float b1 = sx[rl*68 + jj + 1];
                        float h0 = a0 / (1.f + expf(-a0)) * b0;
                        float h1 = a1 / (1.f + expf(-a1)) * b1;
                        split_store2(OH, OL,
                                     rowg*D_FF + (size_t)blockIdx.x*64 + jj,
                                     h0, h1);
                    }
                }
            }
        }
    }
    #undef LOAD_STAGE
}

/* ================= V transpose + split ================= */
__global__ __launch_bounds__(256) void vtrans_split_kernel(
    const float* __restrict__ V, __nv_bfloat16* __restrict__ H,
    __nv_bfloat16* __restrict__ L)
{
    __shared__ float t[32][33];
    const int s0 = blockIdx.x * 32, d0 = blockIdx.y * 32, bh = blockIdx.z;
    const int b = bh >> 4, h = bh & 15;
    const int tx = threadIdx.x & 31, ty = threadIdx.x >> 5;
    #pragma unroll
    for (int j = 0; j < 4; j++) {
        int s = s0 + ty + j*8;
        t[ty + j*8][tx] = V[((size_t)(b*SEQ + s))*D_MODEL + h*DK + d0 + tx];
    }
    __syncthreads();
    #pragma unroll
    for (int j = 0; j < 4; j++) {
        int d = d0 + ty + j*8;
        float val = t[tx][ty + j*8];
        __nv_bfloat16 hi = __float2bfloat16(val);
        __nv_bfloat16 lo = __float2bfloat16(val - __bfloat162float(hi));
        size_t idx = ((size_t)bh*DK + d)*SEQ + s0 + tx;
        H[idx] = hi; L[idx] = lo;
    }
}

/* ================= HMMA causal flash attention (bf16x3) ================= */
#define ATTN_SMEM  (192*1024)

__global__ __launch_bounds__(256, 1) void attn_hmma_kernel(
    const __nv_bfloat16* __restrict__ Qh, const __nv_bfloat16* __restrict__ Ql,
    const __nv_bfloat16* __restrict__ Kh, const __nv_bfloat16* __restrict__ Kl,
    const __nv_bfloat16* __restrict__ Vh, const __nv_bfloat16* __restrict__ Vl,
    __nv_bfloat16* __restrict__ Oh, __nv_bfloat16* __restrict__ Ol)
{
    extern __shared__ char smem[];
    const uint32_t sb  = smem_u32(smem);
    const uint32_t sQh = sb, sQl = sb + 32768;
    const int qb = (int)gridDim.x - 1 - (int)blockIdx.x;
    const int bh = blockIdx.y;
    const int b = bh >> 4, h = bh & 15;
    const int tid = threadIdx.x, wid = tid >> 5, lane = tid & 31;
    const int r0 = lane >> 2, qd = lane & 3, lrow = lane & 15, lu = lane >> 4;

    const size_t qrow0 = (size_t)b*SEQ + (size_t)qb*128;
    const size_t krow0 = (size_t)b*SEQ;
    const int hoff = h*DK;
    const size_t vbase = (size_t)bh*DK*SEQ;
    const int NKB = 2*qb + 2;

    #pragma unroll
    for (int it = 0; it < 8; it++) {
        int lin = it*256 + tid;
        int r = lin >> 4, un = lin & 15;
        uint32_t dsw = r*256 + ((un>>3)<<7) + (((un&7) ^ (r&7)) << 4);
        const void* gh = Qh + (qrow0 + r)*D_MODEL + hoff + un*8;
        const void* gl = Ql + (qrow0 + r)*D_MODEL + hoff + un*8;
        asm volatile("cp.async.cg.shared.global [%0], [%1], 16;" :: "r"(sQh+dsw), "l"(gh));
        asm volatile("cp.async.cg.shared.global [%0], [%1], 16;" :: "r"(sQl+dsw), "l"(gl));
    }

    #define LOAD_KV(kb_, s_) do {                                                  \
        uint32_t _st = sb + 65536 + (uint32_t)(s_)*65536;                          \
        size_t _kr = krow0 + (size_t)(kb_)*64;                                     \
        _Pragma("unroll")                                                          \
        for (int _it = 0; _it < 4; _it++) {                                        \
            int _lin = _it*256 + tid;                                              \
            int _r = _lin >> 4, _un = _lin & 15;                                   \
            uint32_t _d = _r*256 + ((_un>>3)<<7) + (((_un&7) ^ (_r&7)) << 4);      \
            const void* _g1 = Kh + (_kr + _r)*D_MODEL + hoff + _un*8;              \
            const void* _g2 = Kl + (_kr + _r)*D_MODEL + hoff + _un*8;              \
            asm volatile("cp.async.cg.shared.global [%0], [%1], 16;"               \
                         :: "r"(_st+_d), "l"(_g1));                                \
            asm volatile("cp.async.cg.shared.global [%0], [%1], 16;"               \
                         :: "r"(_st+16384+_d), "l"(_g2));                          \
        }                                                                          \
        _Pragma("unroll")                                                          \
        for (int _it = 0; _it < 4; _it++) {                                        \
            int _lin = _it*256 + tid;                                              \
            int _r = _lin >> 3, _u = _lin & 7;                                     \
            uint32_t _d = _r*128 + ((_u ^ (_r&7)) << 4);                           \
            const void* _g1 = Vh + vbase + (size_t)_r*SEQ + (size_t)(kb_)*64 + _u*8; \
            const void* _g2 = Vl + vbase + (size_t)_r*SEQ + (size_t)(kb_)*64 + _u*8; \
            asm volatile("cp.async.cg.shared.global [%0], [%1], 16;"               \
                         :: "r"(_st+32768+_d), "l"(_g1));                          \
            asm volatile("cp.async.cg.shared.global [%0], [%1], 16;"               \
                         :: "r"(_st+49152+_d), "l"(_g2));                          \
        }                                                                          \
        asm volatile("cp.async.commit_group;" ::: "memory");                       \
    } while (0)

    LOAD_KV(0, 0);
    LOAD_KV(1, 1);

    float m0 = -1e30f, m1 = -1e30f, l0 = 0.f, l1 = 0.f;
    float oacc[16][4];
    #pragma unroll
    for (int i = 0; i < 16; i++)
        #pragma unroll
        for (int c = 0; c < 4; c++) oacc[i][c] = 0.f;

    for (int kb = 0; kb < NKB; kb++) {
        if (kb + 1 < NKB) asm volatile("cp.async.wait_group 1;" ::: "memory");
        else              asm volatile("cp.async.wait_group 0;" ::: "memory");
        __syncthreads();
        const uint32_t st = sb + 65536 + (uint32_t)(kb & 1)*65536;

        float sacc[8][4];
        #pragma unroll
        for (int i = 0; i < 8; i++)
            #pragma unroll
            for (int c = 0; c < 4; c++) sacc[i][c] = 0.f;

        #pragma unroll
        for (int kk = 0; kk < 8; kk++) {
            const int un = kk*2 + lu;
            const int arow = wid*16 + lrow;
            const uint32_t aoff = arow*256 + ((un>>3)<<7) + (((un&7) ^ (arow&7)) << 4);
            uint32_t ah0,ah1,ah2,ah3, al0,al1,al2,al3;
            LDSM_X4(ah0,ah1,ah2,ah3, sQh + aoff);
            LDSM_X4(al0,al1,al2,al3, sQl + aoff);
            uint32_t bh_[4][4], bl_[4][4];
            #pragma unroll
            for (int nf2 = 0; nf2 < 4; nf2++) {
                const int brow = nf2*16 + lrow;
                const uint32_t boff = brow*256 + ((un>>3)<<7) + (((un&7) ^ (brow&7)) << 4);
                LDSM_X4(bh_[nf2][0], bh_[nf2][1], bh_[nf2][2], bh_[nf2][3], st + boff);
                LDSM_X4(bl_[nf2][0], bl_[nf2][1], bl_[nf2][2], bl_[nf2][3], st + 16384 + boff);
            }
            #pragma unroll
            for (int nf = 0; nf < 8; nf++) {
                const int n2 = nf >> 1, sl = nf & 1;
                MMA16816(sacc[nf], ah0,ah1,ah2,ah3, bh_[n2][sl], bh_[n2][sl+2]);
                MMA16816(sacc[nf], ah0,ah1,ah2,ah3, bl_[n2][sl], bl_[n2][sl+2]);
                MMA16816(sacc[nf], al0,al1,al2,al3, bh_[n2][sl], bh_[n2][sl+2]);
            }
        }

        if (kb >= 2*qb) {
            const int rg0 = qb*128 + wid*16 + r0;
            #pragma unroll
            for (int nf = 0; nf < 8; nf++) {
                const int cg = kb*64 + nf*8 + qd*2;
                if (cg     > rg0)     sacc[nf][0] = -1e30f;
                if (cg + 1 > rg0)     sacc[nf][1] = -1e30f;
                if (cg     > rg0 + 8) sacc[nf][2] = -1e30f;
                if (cg + 1 > rg0 + 8) sacc[nf][3] = -1e30f;
            }
        }

        float mx0 = -1e30f, mx1 = -1e30f;
        #pragma unroll
        for (int nf = 0; nf < 8; nf++) {
            mx0 = fmaxf(mx0, fmaxf(sacc[nf][0], sacc[nf][1]));
            mx1 = fmaxf(mx1, fmaxf(sacc[nf][2], sacc[nf][3]));
        }
        mx0 = fmaxf(mx0, __shfl_xor_sync(0xffffffffu, mx0, 1));
        mx0 = fmaxf(mx0, __shfl_xor_sync(0xffffffffu, mx0, 2));
        mx1 = fmaxf(mx1, __shfl_xor_sync(0xffffffffu, mx1, 1));
        mx1 = fmaxf(mx1, __shfl_xor_sync(0xffffffffu, mx1, 2));
        const float mn0 = fmaxf(m0, mx0), mn1 = fmaxf(m1, mx1);
        const float c0 = exp2f(m0 - mn0), c1 = exp2f(m1 - mn1);
        float s0 = 0.f, s1 = 0.f;
        #pragma unroll
        for (int nf = 0; nf < 8; nf++) {
            sacc[nf][0] = exp2f(sacc[nf][0] - mn0); s0 += sacc[nf][0];
            sacc[nf][1] = exp2f(sacc[nf][1] - mn0); s0 += sacc[nf][1];
            sacc[nf][2] = exp2f(sacc[nf][2] - mn1); s1 += sacc[nf][2];
            sacc[nf][3] = exp2f(sacc[nf][3] - mn1); s1 += sacc[nf][3];
        }
        s0 += __shfl_xor_sync(0xffffffffu, s0, 1);
        s0 += __shfl_xor_sync(0xffffffffu, s0, 2);
        s1 += __shfl_xor_sync(0xffffffffu, s1, 1);
        s1 += __shfl_xor_sync(0xffffffffu, s1, 2);
        l0 = l0*c0 + s0; l1 = l1*c1 + s1; m0 = mn0; m1 = mn1;
        #pragma unroll
        for (int nf = 0; nf < 16; nf++) {
            oacc[nf][0] *= c0; oacc[nf][1] *= c0;
            oacc[nf][2] *= c1; oacc[nf][3] *= c1;
        }

        #pragma unroll
        for (int ks = 0; ks < 4; ks++) {
            uint32_t pah[4], pal[4];
            split_pack2(sacc[2*ks][0],   sacc[2*ks][1],   pah[0], pal[0]);
            split_pack2(sacc[2*ks][2],   sacc[2*ks][3],   pah[1], pal[1]);
            split_pack2(sacc[2*ks+1][0], sacc[2*ks+1][1], pah[2], pal[2]);
            split_pack2(sacc[2*ks+1][2], sacc[2*ks+1][3], pah[3], pal[3]);
            const int un = ks*2 + lu;
            #pragma unroll
            for (int nf2 = 0; nf2 < 8; nf2++) {
                const int vrow = nf2*16 + lrow;
                const uint32_t voff = vrow*128 + ((un ^ (vrow&7)) << 4);
                uint32_t vh0,vh1,vh2,vh3, vl0,vl1,vl2,vl3;
                LDSM_X4(vh0,vh1,vh2,vh3, st + 32768 + voff);
                LDSM_X4(vl0,vl1,vl2,vl3, st + 49152 + voff);
                MMA16816(oacc[nf2*2+0], pah[0],pah[1],pah[2],pah[3], vh0, vh2);
                MMA16816(oacc[nf2*2+0], pah[0],pah[1],pah[2],pah[3], vl0, vl2);
                MMA16816(oacc[nf2*2+0], pal[0],pal[1],pal[2],pal[3], vh0, vh2);
                MMA16816(oacc[nf2*2+1], pah[0],pah[1],pah[2],pah[3], vh1, vh3);
                MMA16816(oacc[nf2*2+1], pah[0],pah[1],pah[2],pah[3], vl1, vl3);
                MMA16816(oacc[nf2*2+1], pal[0],pal[1],pal[2],pal[3], vh1, vh3);
            }
        }
        __syncthreads();
        if (kb + 2 < NKB) LOAD_KV(kb + 2, kb & 1);
    }

    const float inv0 = 1.f / l0, inv1 = 1.f / l1;
    const size_t row0 = qrow0 + wid*16 + r0;
    #pragma unroll
    for (int nf = 0; nf < 16; nf++) {
        const size_t c = (size_t)hoff + nf*8 + qd*2;
        split_store2(Oh, Ol, row0*D_MODEL + c,
                     oacc[nf][0]*inv0, oacc[nf][1]*inv0);
        split_store2(Oh, Ol, (row0+8)*D_MODEL + c,
                     oacc[nf][2]*inv1, oacc[nf][3]*inv1);
    }
    #undef LOAD_KV
}

/* ================= launch ================= */
extern "C" void kernel_launch(void* const* d_in, const int* in_sizes, int n_in,
                              void* d_out, int out_size)
{
    const float* x  = (const float*)d_in[0];
    const float* Wq = (const float*)d_in[1];
    const float* Wk = (const float*)d_in[2];
    const float* Wv = (const float*)d_in[3];
    const float* Wo = (const float*)d_in[4];
    const float* W1 = (const float*)d_in[5];
    const float* W2 = (const float*)d_in[6];
    const float* W3 = (const float*)d_in[7];
    const float* g1 = (const float*)d_in[8];
    const float* g2 = (const float*)d_in[9];
    float* out = (float*)d_out;

    float *v, *res;
    cudaGetSymbolAddress((void**)&v,   g_v);
    cudaGetSymbolAddress((void**)&res, g_res);

    __nv_bfloat16 *xnh,*xnl,*ath,*atl,*f1h,*f1l;
    __nv_bfloat16 *qh,*ql,*kh,*kl,*vth,*vtl;
    __nv_bfloat16 *wqkvh,*wqkvl,*woh,*wol,*w13h,*w13l,*w2h,*w2l;
    cudaGetSymbolAddress((void**)&xnh, g_xnh); cudaGetSymbolAddress((void**)&xnl, g_xnl);
    cudaGetSymbolAddress((void**)&ath, g_ath); cudaGetSymbolAddress((void**)&atl, g_atl);
    cudaGetSymbolAddress((void**)&f1h, g_f1h); cudaGetSymbolAddress((void**)&f1l, g_f1l);
    cudaGetSymbolAddress((void**)&qh,  g_qh);  cudaGetSymbolAddress((void**)&ql,  g_ql);
    cudaGetSymbolAddress((void**)&kh,  g_kh);  cudaGetSymbolAddress((void**)&kl,  g_kl);
    cudaGetSymbolAddress((void**)&vth, g_vth); cudaGetSymbolAddress((void**)&vtl, g_vtl);
    cudaGetSymbolAddress((void**)&wqkvh, g_wqkvh); cudaGetSymbolAddress((void**)&wqkvl, g_wqkvl);
    cudaGetSymbolAddress((void**)&woh, g_woh); cudaGetSymbolAddress((void**)&wol, g_wol);
    cudaGetSymbolAddress((void**)&w13h, g_w13h); cudaGetSymbolAddress((void**)&w13l, g_w13l);
    cudaGetSymbolAddress((void**)&w2h, g_w2h); cudaGetSymbolAddress((void**)&w2l, g_w2l);

    cudaFuncSetAttribute(gemm_kernel<0>,
        cudaFuncAttributeMaxDynamicSharedMemorySize, GEMM_SMEM);
    cudaFuncSetAttribute(gemm_kernel<1>,
        cudaFuncAttributeMaxDynamicSharedMemorySize, GEMM_SMEM);
    cudaFuncSetAttribute(gemm_kernel<2>,
        cudaFuncAttributeMaxDynamicSharedMemorySize, GEMM_SMEM);
    cudaFuncSetAttribute(attn_hmma_kernel,
        cudaFuncAttributeMaxDynamicSharedMemorySize, ATTN_SMEM);

    /* 0. all weight splits in one launch */
    {
        size_t total4 = 4*((size_t)D_MODEL*D_MODEL/4) + 3*((size_t)D_FF*D_MODEL/4);
        megasplit_kernel<<<(unsigned)((total4 + 255)/256), 256>>>(
            Wq, Wk, Wv, Wo, W1, W3, W2,
            wqkvh, wqkvl, woh, wol, w13h, w13l, w2h, w2l);
    }

    /* 1. xn = rmsnorm(x, g1) -> split */
    rmsnorm_split_kernel<<<ROWS, 256>>>(x, g1, xnh, xnl);

    /* 2. merged QKV projection; q/k roped+split, v fp32 */
    gemm_kernel<1><<<dim3(48, ROWS/128), 256, GEMM_SMEM>>>(
        xnh, xnl, wqkvh, wqkvl, v, nullptr, qh, ql, kh, kl,
        ROWS, D_MODEL, D_MODEL);

    /* 3. V transpose + split */
    vtrans_split_kernel<<<dim3(SEQ/32, DK/32, BATCH*NH), 256>>>(v, vth, vtl);

    /* 4. attention */
    attn_hmma_kernel<<<dim3(SEQ/128, BATCH*NH), 256, ATTN_SMEM>>>(
        qh, ql, kh, kl, vth, vtl, ath, atl);

    /* 5. res = x + att @ Wo^T */
    gemm_kernel<0><<<dim3(16, ROWS/128), 256, GEMM_SMEM>>>(
        ath, atl, woh, wol, res, x, nullptr, nullptr, nullptr, nullptr,
        ROWS, D_MODEL, D_MODEL);

    /* 6. xn2 = rmsnorm(res, g2) -> split */
    rmsnorm_split_kernel<<<ROWS, 256>>>(res, g2, xnh, xnl);

    /* 7. merged W13 GEMM + fused swiglu -> h split */
    gemm_kernel<2><<<dim3(86, ROWS/128), 256, GEMM_SMEM>>>(
        xnh, xnl, w13h, w13l, nullptr, nullptr, f1h, f1l, nullptr, nullptr,
        ROWS, D_FF, D_MODEL);

    /* 8. out = res + h @ W2^T */
    gemm_kernel<0><<<dim3(16, ROWS/128), 256, GEMM_SMEM>>>(
        f1h, f1l, w2h, w2l, out, res, nullptr, nullptr, nullptr, nullptr,
        ROWS, D_MODEL, D_FF);
}